// round 15
// baseline (speedup 1.0000x reference)
#include <cuda_runtime.h>
#include <cuda_bf16.h>
#include <math.h>
#include <stdint.h>

// ---------------- problem constants ----------------
#define B_      4
#define L_      8192
#define DMODEL  256
#define DINNER  512
#define DSTATE  64
#define NH      4
#define HD      128
#define CHUNKSZ 128
#define NC      64
#define CONVD   640
#define DPROJ   1156
#define DPROJ_PAD 1280
#define HIMG    256
#define WIMG    512
#define HO      64
#define WO      128

// ---------------- static scratch ----------------
__device__ float g_zx   [(size_t)2*B_*L_*DPROJ];
__device__ float g_xbc  [(size_t)B_*L_*CONVD];     // stream 0 only (conv+silu)
__device__ float g_dt   [(size_t)2*B_*L_*NH];
__device__ float g_cum  [(size_t)2*B_*L_*NH];
__device__ float g_y    [(size_t)2*B_*L_*DINNER];
__device__ float g_state[(size_t)2*B_*NC*NH*HD*DSTATE];
__device__ float g_hprev[(size_t)2*B_*NC*NH*HD*DSTATE];
__device__ __nv_bfloat16 g_ah[(size_t)2*B_*L_*DINNER];
__device__ __nv_bfloat16 g_al[(size_t)2*B_*L_*DINNER];
__device__ __nv_bfloat16 g_bh[(size_t)DPROJ_PAD*DMODEL];
__device__ __nv_bfloat16 g_bl[(size_t)DPROJ_PAD*DMODEL];

// xBC row accessor: stream 0 lives in g_xbc (post conv+silu);
// stream 1 is the raw in_proj slice, read straight from g_zx.
__device__ __forceinline__ const float* xbc_row(int sbb, size_t l) {
    return (sbb < B_) ? &g_xbc[((size_t)sbb*L_ + l)*CONVD]
                      : &g_zx [((size_t)sbb*L_ + l)*DPROJ + 512];
}

// ---------------- mma.sync helpers ----------------
__device__ __forceinline__ uint32_t smem_to_u32(const void* p) {
    uint32_t a;
    asm("{ .reg .u64 t; cvta.to.shared.u64 t, %1; cvt.u32.u64 %0, t; }" : "=r"(a) : "l"(p));
    return a;
}
__device__ __forceinline__ uint32_t swz(uint32_t o) { return o ^ ((o >> 3) & 0x70); }

__device__ __forceinline__ void cp_async16(uint32_t saddr, const void* gptr) {
    asm volatile("cp.async.cg.shared.global [%0], [%1], 16;" :: "r"(saddr), "l"(gptr));
}
#define CP_COMMIT() asm volatile("cp.async.commit_group;" ::: "memory")
#define CP_WAIT(n)  asm volatile("cp.async.wait_group %0;" :: "n"(n) : "memory")

__device__ __forceinline__ void ldsm_x4(uint32_t* r, uint32_t addr) {
    asm volatile("ldmatrix.sync.aligned.m8n8.x4.shared.b16 {%0,%1,%2,%3}, [%4];"
        : "=r"(r[0]), "=r"(r[1]), "=r"(r[2]), "=r"(r[3]) : "r"(addr));
}
__device__ __forceinline__ void ldsm_x2(uint32_t* r, uint32_t addr) {
    asm volatile("ldmatrix.sync.aligned.m8n8.x2.shared.b16 {%0,%1}, [%2];"
        : "=r"(r[0]), "=r"(r[1]) : "r"(addr));
}
__device__ __forceinline__ void mma_bf16(float* c, const uint32_t* a, const uint32_t* b) {
    asm volatile("mma.sync.aligned.m16n8k16.row.col.f32.bf16.bf16.f32 "
        "{%0,%1,%2,%3}, {%4,%5,%6,%7}, {%8,%9}, {%0,%1,%2,%3};"
        : "+f"(c[0]), "+f"(c[1]), "+f"(c[2]), "+f"(c[3])
        : "r"(a[0]), "r"(a[1]), "r"(a[2]), "r"(a[3]), "r"(b[0]), "r"(b[1]));
}
__device__ __forceinline__ void split_bf16(float v, __nv_bfloat16& h, __nv_bfloat16& l) {
    h = __float2bfloat16_rn(v);
    l = __float2bfloat16_rn(v - __bfloat162float(h));
}

// ============================================================================
// split-bf16 tensor GEMM, 3-stage cp.async pipeline (FINAL)
// ============================================================================
__global__ void __launch_bounds__(256)
mma_gemm(const __nv_bfloat16* __restrict__ Ah, const __nv_bfloat16* __restrict__ Al,
         const __nv_bfloat16* __restrict__ Bh, const __nv_bfloat16* __restrict__ Bl,
         float* __restrict__ C, int M, int N, int K) {
    extern __shared__ char smem[];
    uint32_t sbase = smem_to_u32(smem);
    int tid = threadIdx.x, wid = tid >> 5, lane = tid & 31;
    int m0 = blockIdx.y * 128, n0 = blockIdx.x * 128;
    int wm = wid & 3, wn = wid >> 2;

    float acc[2][8][4];
    #pragma unroll
    for (int mt = 0; mt < 2; mt++)
        #pragma unroll
        for (int nt = 0; nt < 8; nt++)
            #pragma unroll
            for (int q = 0; q < 4; q++) acc[mt][nt][q] = 0.f;

    const int KT = K >> 6;
    int lrow = tid >> 3, lc8 = tid & 7;

    auto issue = [&](int kt) {
        uint32_t so = (uint32_t)(kt % 3) * 65536u;
        #pragma unroll
        for (int u = 0; u < 4; u++) {
            int row = lrow + 32 * u;
            uint32_t sw = swz((uint32_t)row * 128 + lc8 * 16);
            size_t aoff = ((size_t)(m0 + row) * K + kt * 64 + lc8 * 8);
            size_t boff = ((size_t)(n0 + row) * K + kt * 64 + lc8 * 8);
            cp_async16(sbase + so + sw,         Ah + aoff);
            cp_async16(sbase + so + 16384 + sw, Al + aoff);
            cp_async16(sbase + so + 32768 + sw, Bh + boff);
            cp_async16(sbase + so + 49152 + sw, Bl + boff);
        }
        CP_COMMIT();
    };

    issue(0);
    if (KT > 1) issue(1);

    for (int kt = 0; kt < KT; kt++) {
        if (kt + 1 < KT) CP_WAIT(1); else CP_WAIT(0);
        __syncthreads();
        if (kt + 2 < KT) issue(kt + 2);

        uint32_t so = (uint32_t)(kt % 3) * 65536u;
        #pragma unroll
        for (int ks = 0; ks < 4; ks++) {
            uint32_t ah[2][4], alr[2][4];
            #pragma unroll
            for (int mt = 0; mt < 2; mt++) {
                int row = wm * 32 + mt * 16 + (lane & 15);
                int kb  = ks * 32 + ((lane >> 4) << 4);
                uint32_t off = swz((uint32_t)row * 128 + kb);
                ldsm_x4(ah[mt],  sbase + so + off);
                ldsm_x4(alr[mt], sbase + so + 16384 + off);
            }
            int l2 = lane & 15;
            int nrow = wn * 64 + (l2 & 7);
            int kb2  = ks * 32 + ((l2 >> 3) << 4);
            #pragma unroll
            for (int nt = 0; nt < 8; nt++) {
                uint32_t bh[2], bl[2];
                uint32_t off = swz((uint32_t)(nrow + nt * 8) * 128 + kb2);
                ldsm_x2(bh, sbase + so + 32768 + off);
                ldsm_x2(bl, sbase + so + 49152 + off);
                #pragma unroll
                for (int mt = 0; mt < 2; mt++) {
                    mma_bf16(acc[mt][nt], ah[mt],  bh);
                    mma_bf16(acc[mt][nt], ah[mt],  bl);
                    mma_bf16(acc[mt][nt], alr[mt], bh);
                }
            }
        }
    }

    int r_base = m0 + wm * 32 + (lane >> 2);
    int c_base = n0 + wn * 64 + 2 * (lane & 3);
    #pragma unroll
    for (int mt = 0; mt < 2; mt++) {
        #pragma unroll
        for (int nt = 0; nt < 8; nt++) {
            int c = c_base + nt * 8;
            if (c < N) {
                int r = r_base + mt * 16;
                *(float2*)&C[(size_t)r * N + c]       = make_float2(acc[mt][nt][0], acc[mt][nt][1]);
                *(float2*)&C[(size_t)(r + 8) * N + c] = make_float2(acc[mt][nt][2], acc[mt][nt][3]);
            }
        }
    }
}

// ============================================================================
// weight conversion
// ============================================================================
__global__ void cvt_split_pad(const float* __restrict__ src,
                              __nv_bfloat16* __restrict__ hi,
                              __nv_bfloat16* __restrict__ lo,
                              int N, int K, int Npad) {
    size_t i = (size_t)blockIdx.x * 256 + threadIdx.x;
    if (i >= (size_t)Npad * K) return;
    int n = (int)(i / K);
    float v = (n < N) ? src[i] : 0.f;
    __nv_bfloat16 h, l; split_bf16(v, h, l);
    hi[i] = h; lo[i] = l;
}

// ============================================================================
// 1. Downsample conv -> split-bf16 A for in_proj.
//    v2: weight tile transposed in smem (sw[j][c], j-major) so the inner-loop
//    weight reads are lane-consecutive (conflict-free) instead of stride-48
//    (16-way bank conflict).  Math order unchanged.
// ============================================================================
__global__ void downsample_kernel(const float* __restrict__ left,
                                  const float* __restrict__ right,
                                  const float* __restrict__ dw,
                                  const float* __restrict__ db) {
    extern __shared__ float sm[];
    float* sw = sm;             // [48][256]  (j-major, transposed)
    float* sp = sm + 48*DMODEL; // [16][48]
    int bi = blockIdx.x;
    int wt = bi % (WO/16);
    int oh = (bi / (WO/16)) % HO;
    int b  = (bi / (WO/16 * HO)) % B_;
    int s  = bi / (WO/16 * HO * B_);
    const float* img = s ? right : left;
    int tid = threadIdx.x;
    // fill transposed: c = i&255 (lane-consecutive smem stores, conflict-free)
    for (int i = tid; i < DMODEL*48; i += 256) {
        int c = i & 255, j = i >> 8;
        sw[j*DMODEL + c] = dw[c*48 + j];
    }
    int ow0 = wt * 16;
    for (int i = tid; i < 16*48; i += 256) {
        int pos = i / 48, j = i % 48;
        int ci = j / 16, kh = (j % 16) / 4, kw = j % 4;
        sp[i] = img[((size_t)(b*3 + ci)*HIMG + (oh*4 + kh))*WIMG + (ow0 + pos)*4 + kw];
    }
    __syncthreads();
    int c = tid;
    float bias = db[c];
    for (int pos = 0; pos < 16; pos++) {
        float acc = bias;
        #pragma unroll
        for (int j = 0; j < 48; j++) acc += sp[pos*48 + j] * sw[j*DMODEL + c];
        int l = oh*WO + ow0 + pos;
        size_t off = ((size_t)(s*B_ + b)*L_ + l)*DMODEL + c;
        __nv_bfloat16 h, lo; split_bf16(acc, h, lo);
        g_ah[off] = h;
        g_al[off] = lo;
    }
}

// ============================================================================
// 3. conv1d + silu, stream 0 only, sliding window (8 l-positions / thread)
// ============================================================================
__global__ void conv_split_kernel_v2(const float* __restrict__ cw,
                                     const float* __restrict__ cb) {
    int idx = blockIdx.x * 256 + threadIdx.x;
    const int NC4 = CONVD/4;         // 160
    int c4 = idx % NC4;
    int t  = idx / NC4;              // (sb, l-tile)
    if (t >= B_ * (L_/8)) return;
    int lt = t % (L_/8);
    int sb = t / (L_/8);
    int l0 = lt * 8;
    int ch = c4 * 4;

    float4 w0 = *(const float4*)&cw[(ch+0)*4];
    float4 w1 = *(const float4*)&cw[(ch+1)*4];
    float4 w2 = *(const float4*)&cw[(ch+2)*4];
    float4 w3 = *(const float4*)&cw[(ch+3)*4];
    float4 bias = *(const float4*)&cb[ch];

    float4 v[11];
    #pragma unroll
    for (int r = 0; r < 11; r++) {
        int ls = l0 - 3 + r;
        v[r] = (ls >= 0) ? *(const float4*)&g_zx[((size_t)sb*L_ + ls)*DPROJ + 512 + ch]
                         : make_float4(0.f, 0.f, 0.f, 0.f);
    }

    #pragma unroll
    for (int i = 0; i < 8; i++) {
        float a0 = bias.x + w0.x*v[i].x + w0.y*v[i+1].x + w0.z*v[i+2].x + w0.w*v[i+3].x;
        float a1 = bias.y + w1.x*v[i].y + w1.y*v[i+1].y + w1.z*v[i+2].y + w1.w*v[i+3].y;
        float a2 = bias.z + w2.x*v[i].z + w2.y*v[i+1].z + w2.z*v[i+2].z + w2.w*v[i+3].z;
        float a3 = bias.w + w3.x*v[i].w + w3.y*v[i+1].w + w3.z*v[i+2].w + w3.w*v[i+3].w;
        float4 out;
        out.x = a0 / (1.f + __expf(-a0));
        out.y = a1 / (1.f + __expf(-a1));
        out.z = a2 / (1.f + __expf(-a2));
        out.w = a3 / (1.f + __expf(-a3));
        *(float4*)&g_xbc[((size_t)sb*L_ + l0 + i)*CONVD + ch] = out;
    }
}

// ============================================================================
// 4. dt softplus
// ============================================================================
__global__ void dt_kernel(const float* __restrict__ dt_bias) {
    size_t idx = (size_t)blockIdx.x * 256 + threadIdx.x;
    if (idx >= (size_t)2*B_*L_*NH) return;
    int h = (int)(idx % NH);
    size_t row = idx / NH;
    float v = g_zx[row*DPROJ + (DINNER + CONVD) + h] + dt_bias[h];
    g_dt[idx] = (v > 20.f) ? v : log1pf(__expf(v));
}

// ============================================================================
// 5. per-chunk cumsum (warp-parallel)
// ============================================================================
__global__ void cum_kernel_v2(const float* __restrict__ A_log) {
    int gw = blockIdx.x * 8 + (threadIdx.x >> 5);
    int lane = threadIdx.x & 31;
    if (gw >= 2*B_*NC*NH) return;
    int h = gw % NH;
    int c = (gw / NH) % NC;
    int sb = gw / (NH * NC);
    float An = -__expf(A_log[h]);
    size_t base = ((size_t)sb*L_ + c*CHUNKSZ + lane*4)*NH + h;
    float v0 = g_dt[base], v1 = g_dt[base + NH], v2 = g_dt[base + 2*NH], v3 = g_dt[base + 3*NH];
    float p0 = v0, p1 = p0 + v1, p2 = p1 + v2, p3 = p2 + v3;
    float incl = p3;
    #pragma unroll
    for (int o = 1; o < 32; o <<= 1) {
        float t = __shfl_up_sync(0xFFFFFFFFu, incl, o);
        if (lane >= o) incl += t;
    }
    float ex = incl - p3;
    g_cum[base]        = An * (ex + p0);
    g_cum[base + NH]   = An * (ex + p1);
    g_cum[base + 2*NH] = An * (ex + p2);
    g_cum[base + 3*NH] = An * (ex + p3);
}

// ============================================================================
// 6. Intra-chunk SSD via tensor cores (FINAL)
// ============================================================================
#define CK_XT_H(p) (2048u + (uint32_t)(p)*16384u)
#define CK_XT_L(p) (34816u + (uint32_t)(p)*16384u)
#define CK_BW_H(p) (67584u + (uint32_t)(p)*8192u)
#define CK_BW_L(p) (83968u + (uint32_t)(p)*8192u)
#define CK_R1      100352u
#define CK_GH(p)   (CK_R1 + (uint32_t)(p)*16384u)
#define CK_GL(p)   (CK_R1 + 32768u + (uint32_t)(p)*16384u)
#define CK_SMEM    165888

__global__ void __launch_bounds__(256)
chunk_kernel_v2(const float* __restrict__ Dv) {
    extern __shared__ char smraw[];
    uint32_t sbase = smem_to_u32(smraw);
    float* cum_s = (float*)smraw;
    float* dts_s = (float*)(smraw + 512);
    float* wj_s  = (float*)(smraw + 1024);

    int bi = blockIdx.x, tid = threadIdx.x;
    int wid = tid >> 5, lane = tid & 31;
    int wm = wid & 3, wn = wid >> 2;
    int l2 = lane & 15;
    int h  = bi % NH;
    int c  = (bi / NH) % NC;
    int b  = (bi / (NH*NC)) % B_;
    int s  = bi / (NH*NC*B_);
    int sb  = s*B_ + b;
    int sbo = (1 - s)*B_ + b;
    size_t l0 = (size_t)c * CHUNKSZ;

    if (tid < 128) {
        size_t off = ((size_t)sb*L_ + l0 + tid)*NH + h;
        cum_s[tid] = g_cum[off];
        dts_s[tid] = g_dt[off];
    }
    __syncthreads();
    if (tid < 128) wj_s[tid] = dts_s[tid] * __expf(cum_s[127] - cum_s[tid]);
    __syncthreads();

    for (int idx = tid; idx < 128*64; idx += 256) {
        int j = idx >> 6, n = idx & 63;
        float cv = xbc_row(sb,  l0 + j)[576 + n];
        float bv = xbc_row(sbo, l0 + j)[512 + n];
        __nv_bfloat16 hh, ll;
        uint32_t so = swz((uint32_t)j*128 + n*2);
        split_bf16(cv, hh, ll);
        *(__nv_bfloat16*)(smraw + CK_R1 + so)         = hh;
        *(__nv_bfloat16*)(smraw + CK_R1 + 16384 + so) = ll;
        split_bf16(bv, hh, ll);
        *(__nv_bfloat16*)(smraw + CK_R1 + 32768 + so) = hh;
        *(__nv_bfloat16*)(smraw + CK_R1 + 49152 + so) = ll;
        float bw = bv * wj_s[j];
        split_bf16(bw, hh, ll);
        uint32_t st = swz((uint32_t)n*128 + (j & 63)*2);
        int pan = j >> 6;
        *(__nv_bfloat16*)(smraw + CK_BW_H(pan) + st) = hh;
        *(__nv_bfloat16*)(smraw + CK_BW_L(pan) + st) = ll;
    }
    for (int idx = tid; idx < 128*128; idx += 256) {
        int j = idx >> 7, p = idx & 127;
        float xv = xbc_row(sbo, l0 + j)[h*HD + p];
        __nv_bfloat16 hh, ll; split_bf16(xv, hh, ll);
        int pan = j >> 6;
        uint32_t st = swz((uint32_t)p*128 + (j & 63)*2);
        *(__nv_bfloat16*)(smraw + CK_XT_H(pan) + st) = hh;
        *(__nv_bfloat16*)(smraw + CK_XT_L(pan) + st) = ll;
    }
    __syncthreads();

    // phase A: G = C * B^T
    float accg[2][8][4];
    #pragma unroll
    for (int mt = 0; mt < 2; mt++)
        #pragma unroll
        for (int nt = 0; nt < 8; nt++)
            #pragma unroll
            for (int q = 0; q < 4; q++) accg[mt][nt][q] = 0.f;
    #pragma unroll
    for (int ks = 0; ks < 4; ks++) {
        uint32_t ah[2][4], al[2][4];
        #pragma unroll
        for (int mt = 0; mt < 2; mt++) {
            int row = wm*32 + mt*16 + (lane & 15);
            uint32_t off = swz((uint32_t)row*128 + ks*32 + ((lane >> 4) << 4));
            ldsm_x4(ah[mt], sbase + CK_R1 + off);
            ldsm_x4(al[mt], sbase + CK_R1 + 16384 + off);
        }
        #pragma unroll
        for (int nt = 0; nt < 8; nt++) {
            int row = wn*64 + nt*8 + (l2 & 7);
            uint32_t off = swz((uint32_t)row*128 + ks*32 + ((l2 >> 3) << 4));
            uint32_t bh[2], bl[2];
            ldsm_x2(bh, sbase + CK_R1 + 32768 + off);
            ldsm_x2(bl, sbase + CK_R1 + 49152 + off);
            #pragma unroll
            for (int mt = 0; mt < 2; mt++) {
                mma_bf16(accg[mt][nt], ah[mt], bh);
                mma_bf16(accg[mt][nt], ah[mt], bl);
                mma_bf16(accg[mt][nt], al[mt], bh);
            }
        }
    }
    __syncthreads();

    {
        int r0 = lane >> 2, cj = 2*(lane & 3);
        #pragma unroll
        for (int mt = 0; mt < 2; mt++) {
            #pragma unroll
            for (int nt = 0; nt < 8; nt++) {
                int j0 = wn*64 + nt*8 + cj;
                int jl = (j0 & 63);
                #pragma unroll
                for (int half = 0; half < 2; half++) {
                    int i = wm*32 + mt*16 + r0 + half*8;
                    float ci = cum_s[i];
                    float g0 = (j0   <= i) ? accg[mt][nt][half*2]   * __expf(ci - cum_s[j0])   * dts_s[j0]   : 0.f;
                    float g1 = (j0+1 <= i) ? accg[mt][nt][half*2+1] * __expf(ci - cum_s[j0+1]) * dts_s[j0+1] : 0.f;
                    __nv_bfloat16 h0, l0b, h1, l1b;
                    split_bf16(g0, h0, l0b); split_bf16(g1, h1, l1b);
                    uint32_t st = swz((uint32_t)i*128 + jl*2);
                    *(__nv_bfloat162*)(smraw + CK_GH(wn) + st) = __nv_bfloat162(h0, h1);
                    *(__nv_bfloat162*)(smraw + CK_GL(wn) + st) = __nv_bfloat162(l0b, l1b);
                }
            }
        }
    }
    __syncthreads();

    // phase B: Y = G @ X
    {
        float accy[2][8][4];
        #pragma unroll
        for (int mt = 0; mt < 2; mt++)
            #pragma unroll
            for (int nt = 0; nt < 8; nt++)
                #pragma unroll
                for (int q = 0; q < 4; q++) accy[mt][nt][q] = 0.f;
        #pragma unroll
        for (int pan = 0; pan < 2; pan++) {
            #pragma unroll
            for (int ks = 0; ks < 4; ks++) {
                uint32_t gh[2][4], gl[2][4];
                #pragma unroll
                for (int mt = 0; mt < 2; mt++) {
                    int row = wm*32 + mt*16 + (lane & 15);
                    uint32_t off = swz((uint32_t)row*128 + ks*32 + ((lane >> 4) << 4));
                    ldsm_x4(gh[mt], sbase + CK_GH(pan) + off);
                    ldsm_x4(gl[mt], sbase + CK_GL(pan) + off);
                }
                #pragma unroll
                for (int nt = 0; nt < 8; nt++) {
                    int row = wn*64 + nt*8 + (l2 & 7);
                    uint32_t off = swz((uint32_t)row*128 + ks*32 + ((l2 >> 3) << 4));
                    uint32_t xh[2], xl[2];
                    ldsm_x2(xh, sbase + CK_XT_H(pan) + off);
                    ldsm_x2(xl, sbase + CK_XT_L(pan) + off);
                    #pragma unroll
                    for (int mt = 0; mt < 2; mt++) {
                        mma_bf16(accy[mt][nt], gh[mt], xh);
                        mma_bf16(accy[mt][nt], gh[mt], xl);
                        mma_bf16(accy[mt][nt], gl[mt], xh);
                    }
                }
            }
        }
        float Dh = Dv[h];
        int r0 = lane >> 2, cp = 2*(lane & 3);
        #pragma unroll
        for (int mt = 0; mt < 2; mt++) {
            #pragma unroll
            for (int nt = 0; nt < 8; nt++) {
                int p0 = wn*64 + nt*8 + cp;
                #pragma unroll
                for (int half = 0; half < 2; half++) {
                    int i = wm*32 + mt*16 + r0 + half*8;
                    int ipan = i >> 6;
                    uint32_t b0 = swz((uint32_t)p0*128 + (i & 63)*2);
                    uint32_t b1 = swz((uint32_t)(p0+1)*128 + (i & 63)*2);
                    float x0 = __bfloat162float(*(__nv_bfloat16*)(smraw + CK_XT_H(ipan) + b0))
                             + __bfloat162float(*(__nv_bfloat16*)(smraw + CK_XT_L(ipan) + b0));
                    float x1 = __bfloat162float(*(__nv_bfloat16*)(smraw + CK_XT_H(ipan) + b1))
                             + __bfloat162float(*(__nv_bfloat16*)(smraw + CK_XT_L(ipan) + b1));
                    size_t off = ((size_t)sb*L_ + l0 + i)*DINNER + h*HD + p0;
                    *(float2*)&g_y[off] = make_float2(accy[mt][nt][half*2] + Dh*x0,
                                                      accy[mt][nt][half*2+1] + Dh*x1);
                }
            }
        }
    }

    // phase C: S = X^T @ Bw
    {
        float accs[2][4][4];
        #pragma unroll
        for (int mt = 0; mt < 2; mt++)
            #pragma unroll
            for (int nt = 0; nt < 4; nt++)
                #pragma unroll
                for (int q = 0; q < 4; q++) accs[mt][nt][q] = 0.f;
        #pragma unroll
        for (int pan = 0; pan < 2; pan++) {
            #pragma unroll
            for (int ks = 0; ks < 4; ks++) {
                uint32_t xh[2][4], xl[2][4];
                #pragma unroll
                for (int mt = 0; mt < 2; mt++) {
                    int row = wm*32 + mt*16 + (lane & 15);
                    uint32_t off = swz((uint32_t)row*128 + ks*32 + ((lane >> 4) << 4));
                    ldsm_x4(xh[mt], sbase + CK_XT_H(pan) + off);
                    ldsm_x4(xl[mt], sbase + CK_XT_L(pan) + off);
                }
                #pragma unroll
                for (int nt = 0; nt < 4; nt++) {
                    int row = wn*32 + nt*8 + (l2 & 7);
                    uint32_t off = swz((uint32_t)row*128 + ks*32 + ((l2 >> 3) << 4));
                    uint32_t bwh[2], bwl[2];
                    ldsm_x2(bwh, sbase + CK_BW_H(pan) + off);
                    ldsm_x2(bwl, sbase + CK_BW_L(pan) + off);
                    #pragma unroll
                    for (int mt = 0; mt < 2; mt++) {
                        mma_bf16(accs[mt][nt], xh[mt], bwh);
                        mma_bf16(accs[mt][nt], xh[mt], bwl);
                        mma_bf16(accs[mt][nt], xl[mt], bwh);
                    }
                }
            }
        }
        size_t sb0 = (size_t)bi * (HD*DSTATE);
        int r0 = lane >> 2, cn = 2*(lane & 3);
        #pragma unroll
        for (int mt = 0; mt < 2; mt++) {
            #pragma unroll
            for (int nt = 0; nt < 4; nt++) {
                int n0 = wn*32 + nt*8 + cn;
                #pragma unroll
                for (int half = 0; half < 2; half++) {
                    int p = wm*32 + mt*16 + r0 + half*8;
                    *(float2*)&g_state[sb0 + (size_t)p*64 + n0] =
                        make_float2(accs[mt][nt][half*2], accs[mt][nt][half*2+1]);
                }
            }
        }
    }
}

// ============================================================================
// 7. Inter-chunk scan
// ============================================================================
__global__ void scan_kernel_v2() {
    int t   = blockIdx.x >> 3;
    int seg = blockIdx.x & 7;
    int h = t % NH;
    int sb = t / NH;
    int off0 = seg * 1024 + threadIdx.x * 4;
    float4 hreg = make_float4(0.f, 0.f, 0.f, 0.f);
    for (int c = 0; c < NC; c++) {
        float dec = __expf(g_cum[((size_t)sb*L_ + c*CHUNKSZ + 127)*NH + h]);
        size_t o = (((size_t)sb*NC + c)*NH + h) * (HD*DSTATE) + off0;
        *(float4*)&g_hprev[o] = hreg;
        float4 st = *(const float4*)&g_state[o];
        hreg.x = hreg.x*dec + st.x;
        hreg.y = hreg.y*dec + st.y;
        hreg.z = hreg.z*dec + st.z;
        hreg.w = hreg.w*dec + st.w;
    }
}

// ============================================================================
// 8. Inter-chunk contribution via tensor cores
// ============================================================================
__global__ void __launch_bounds__(256)
interchunk_kernel_v2() {
    extern __shared__ char smraw[];
    uint32_t sbase = smem_to_u32(smraw);
    float* cum_s = (float*)smraw;

    int bi = blockIdx.x, tid = threadIdx.x;
    int wid = tid >> 5, lane = tid & 31;
    int wm = wid & 3, wn = wid >> 2;
    int l2 = lane & 15;
    int h  = bi % NH;
    int c  = (bi / NH) % NC;
    int b  = (bi / (NH*NC)) % B_;
    int s  = bi / (NH*NC*B_);
    int sb = s*B_ + b;
    size_t l0 = (size_t)c * CHUNKSZ;
    size_t hbase = (size_t)bi * (HD*DSTATE);

    if (tid < 128) cum_s[tid] = g_cum[((size_t)sb*L_ + l0 + tid)*NH + h];

    for (int idx = tid; idx < 128*64; idx += 256) {
        int r = idx >> 6, n = idx & 63;
        float cv = xbc_row(sb, l0 + r)[576 + n];
        float hv = g_hprev[hbase + idx];
        __nv_bfloat16 hh, ll;
        uint32_t so = swz((uint32_t)r*128 + n*2);
        split_bf16(cv, hh, ll);
        *(__nv_bfloat16*)(smraw + 1024 + so)         = hh;
        *(__nv_bfloat16*)(smraw + 1024 + 16384 + so) = ll;
        split_bf16(hv, hh, ll);
        *(__nv_bfloat16*)(smraw + 1024 + 32768 + so) = hh;
        *(__nv_bfloat16*)(smraw + 1024 + 49152 + so) = ll;
    }
    __syncthreads();

    float acc[2][8][4];
    #pragma unroll
    for (int mt = 0; mt < 2; mt++)
        #pragma unroll
        for (int nt = 0; nt < 8; nt++)
            #pragma unroll
            for (int q = 0; q < 4; q++) acc[mt][nt][q] = 0.f;
    #pragma unroll
    for (int ks = 0; ks < 4; ks++) {
        uint32_t ah[2][4], al[2][4];
        #pragma unroll
        for (int mt = 0; mt < 2; mt++) {
            int row = wm*32 + mt*16 + (lane & 15);
            uint32_t off = swz((uint32_t)row*128 + ks*32 + ((lane >> 4) << 4));
            ldsm_x4(ah[mt], sbase + 1024 + off);
            ldsm_x4(al[mt], sbase + 1024 + 16384 + off);
        }
        #pragma unroll
        for (int nt = 0; nt < 8; nt++) {
            int row = wn*64 + nt*8 + (l2 & 7);
            uint32_t off = swz((uint32_t)row*128 + ks*32 + ((l2 >> 3) << 4));
            uint32_t hh[2], hl[2];
            ldsm_x2(hh, sbase + 1024 + 32768 + off);
            ldsm_x2(hl, sbase + 1024 + 49152 + off);
            #pragma unroll
            for (int mt = 0; mt < 2; mt++) {
                mma_bf16(acc[mt][nt], ah[mt], hh);
                mma_bf16(acc[mt][nt], ah[mt], hl);
                mma_bf16(acc[mt][nt], al[mt], hh);
            }
        }
    }

    int r0 = lane >> 2, cp = 2*(lane & 3);
    #pragma unroll
    for (int mt = 0; mt < 2; mt++) {
        #pragma unroll
        for (int nt = 0; nt < 8; nt++) {
            int p = wn*64 + nt*8 + cp;
            #pragma unroll
            for (int half = 0; half < 2; half++) {
                int i = wm*32 + mt*16 + r0 + half*8;
                float sc = __expf(cum_s[i]);
                size_t off = ((size_t)sb*L_ + l0 + i)*DINNER + h*HD + p;
                float2 v = *(float2*)&g_y[off];
                v.x += sc * acc[mt][nt][half*2];
                v.y += sc * acc[mt][nt][half*2+1];
                *(float2*)&g_y[off] = v;
            }
        }
    }
}

// ============================================================================
// 9. Gated RMSNorm -> split-bf16 A for out_proj
// ============================================================================
__global__ void rmsnorm_kernel(const float* __restrict__ norm_w) {
    int row = blockIdx.x;
    int tid = threadIdx.x;
    __shared__ float red[4];
    size_t ybase = (size_t)row * DINNER;
    size_t zbase = (size_t)row * DPROJ;
    float g[4];
    float ss = 0.f;
    #pragma unroll
    for (int t = 0; t < 4; t++) {
        int d = tid + 128*t;
        float z = g_zx[zbase + d];
        float yv = g_y[ybase + d];
        float gg = yv * (z / (1.f + __expf(-z)));
        g[t] = gg;
        ss += gg*gg;
    }
    #pragma unroll
    for (int o = 16; o > 0; o >>= 1) ss += __shfl_xor_sync(0xFFFFFFFFu, ss, o);
    if ((tid & 31) == 0) red[tid >> 5] = ss;
    __syncthreads();
    float tot = red[0] + red[1] + red[2] + red[3];
    float scale = rsqrtf(tot / (float)DINNER + 1e-5f);
    #pragma unroll
    for (int t = 0; t < 4; t++) {
        int d = tid + 128*t;
        float v = g[t] * scale * norm_w[d];
        __nv_bfloat16 h, l; split_bf16(v, h, l);
        g_ah[ybase + d] = h;
        g_al[ybase + d] = l;
    }
}

// ============================================================================
extern "C" void kernel_launch(void* const* d_in, const int* in_sizes, int n_in,
                              void* d_out, int out_size) {
    const float* left   = (const float*)d_in[0];
    const float* right  = (const float*)d_in[1];
    const float* dw     = (const float*)d_in[2];
    const float* db     = (const float*)d_in[3];
    const float* inpw   = (const float*)d_in[4];
    const float* cw     = (const float*)d_in[5];
    const float* cb     = (const float*)d_in[6];
    const float* dtb    = (const float*)d_in[7];
    const float* alog   = (const float*)d_in[8];
    const float* Dv     = (const float*)d_in[9];
    const float* nw     = (const float*)d_in[10];
    const float* outw   = (const float*)d_in[11];
    float* out          = (float*)d_out;

    float *p_zx;
    __nv_bfloat16 *p_ah, *p_al, *p_bh, *p_bl;
    cudaGetSymbolAddress((void**)&p_zx, g_zx);
    cudaGetSymbolAddress((void**)&p_ah, g_ah);
    cudaGetSymbolAddress((void**)&p_al, g_al);
    cudaGetSymbolAddress((void**)&p_bh, g_bh);
    cudaGetSymbolAddress((void**)&p_bl, g_bl);

    const int ds_smem  = (DMODEL*48 + 16*48) * 4;
    const int mma_smem = 3 * 65536;
    const int ic_smem  = 66560;
    cudaFuncSetAttribute(downsample_kernel,    cudaFuncAttributeMaxDynamicSharedMemorySize, ds_smem);
    cudaFuncSetAttribute(mma_gemm,             cudaFuncAttributeMaxDynamicSharedMemorySize, mma_smem);
    cudaFuncSetAttribute(chunk_kernel_v2,      cudaFuncAttributeMaxDynamicSharedMemorySize, CK_SMEM);
    cudaFuncSetAttribute(interchunk_kernel_v2, cudaFuncAttributeMaxDynamicSharedMemorySize, ic_smem);

    const int M = 2*B_*L_;   // 65536

    // 1. downsample (conflict-free weight tile)
    downsample_kernel<<<2*B_*HO*(WO/16), 256, ds_smem>>>(left, right, dw, db);

    // 2. in_proj
    {
        size_t nb = (size_t)DPROJ_PAD * DMODEL;
        cvt_split_pad<<<(unsigned)((nb + 255)/256), 256>>>(inpw, p_bh, p_bl, DPROJ, DMODEL, DPROJ_PAD);
        dim3 grid(DPROJ_PAD/128, M/128);
        mma_gemm<<<grid, 256, mma_smem>>>(p_ah, p_al, p_bh, p_bl, p_zx, M, DPROJ, DMODEL);
    }

    // 3. conv+silu (stream 0 only; stream 1 read raw from g_zx downstream)
    {
        int total = B_ * (L_/8) * (CONVD/4);
        conv_split_kernel_v2<<<(total + 255)/256, 256>>>(cw, cb);
    }
    {
        size_t tot = (size_t)M*NH;
        dt_kernel<<<(unsigned)((tot + 255)/256), 256>>>(dtb);
    }
    cum_kernel_v2<<<2*B_*NC*NH/8, 256>>>(alog);

    // 6-8. SSD
    chunk_kernel_v2<<<2*B_*NC*NH, 256, CK_SMEM>>>(Dv);
    scan_kernel_v2<<<2*B_*NH*8, 256>>>();
    interchunk_kernel_v2<<<2*B_*NC*NH, 256, ic_smem>>>();

    // 9. rmsnorm
    rmsnorm_kernel<<<M, 128>>>(nw);

    // 10. out_proj
    {
        size_t nb = (size_t)DMODEL * DINNER;
        cvt_split_pad<<<(unsigned)((nb + 255)/256), 256>>>(outw, p_bh, p_bl, DMODEL, DINNER, DMODEL);
        dim3 grid(DMODEL/128, M/128);
        mma_gemm<<<grid, 256, mma_smem>>>(p_ah, p_al, p_bh, p_bl, out, M, DMODEL, DINNER);
    }
}

// round 16
// speedup vs baseline: 1.0336x; 1.0336x over previous
#include <cuda_runtime.h>
#include <cuda_bf16.h>
#include <math.h>
#include <stdint.h>

// ---------------- problem constants ----------------
#define B_      4
#define L_      8192
#define DMODEL  256
#define DINNER  512
#define DSTATE  64
#define NH      4
#define HD      128
#define CHUNKSZ 128
#define NC      64
#define CONVD   640
#define DPROJ   1156
#define DPROJ_PAD 1280
#define HIMG    256
#define WIMG    512
#define HO      64
#define WO      128

// ---------------- static scratch ----------------
__device__ float g_zx   [(size_t)2*B_*L_*DPROJ];
__device__ float g_xbc  [(size_t)B_*L_*CONVD];     // stream 0 only (conv+silu)
__device__ float g_dt   [(size_t)2*B_*L_*NH];
__device__ float g_cum  [(size_t)2*B_*L_*NH];
__device__ float g_y    [(size_t)2*B_*L_*DINNER];
__device__ float g_state[(size_t)2*B_*NC*NH*HD*DSTATE];
__device__ float g_hprev[(size_t)2*B_*NC*NH*HD*DSTATE];
__device__ __nv_bfloat16 g_ah[(size_t)2*B_*L_*DINNER];
__device__ __nv_bfloat16 g_al[(size_t)2*B_*L_*DINNER];
__device__ __nv_bfloat16 g_bh[(size_t)DPROJ_PAD*DMODEL];
__device__ __nv_bfloat16 g_bl[(size_t)DPROJ_PAD*DMODEL];

// xBC row accessor: stream 0 lives in g_xbc (post conv+silu);
// stream 1 is the raw in_proj slice, read straight from g_zx.
__device__ __forceinline__ const float* xbc_row(int sbb, size_t l) {
    return (sbb < B_) ? &g_xbc[((size_t)sbb*L_ + l)*CONVD]
                      : &g_zx [((size_t)sbb*L_ + l)*DPROJ + 512];
}

// ---------------- mma.sync helpers ----------------
__device__ __forceinline__ uint32_t smem_to_u32(const void* p) {
    uint32_t a;
    asm("{ .reg .u64 t; cvta.to.shared.u64 t, %1; cvt.u32.u64 %0, t; }" : "=r"(a) : "l"(p));
    return a;
}
__device__ __forceinline__ uint32_t swz(uint32_t o) { return o ^ ((o >> 3) & 0x70); }

__device__ __forceinline__ void cp_async16(uint32_t saddr, const void* gptr) {
    asm volatile("cp.async.cg.shared.global [%0], [%1], 16;" :: "r"(saddr), "l"(gptr));
}
#define CP_COMMIT() asm volatile("cp.async.commit_group;" ::: "memory")
#define CP_WAIT(n)  asm volatile("cp.async.wait_group %0;" :: "n"(n) : "memory")

__device__ __forceinline__ void ldsm_x4(uint32_t* r, uint32_t addr) {
    asm volatile("ldmatrix.sync.aligned.m8n8.x4.shared.b16 {%0,%1,%2,%3}, [%4];"
        : "=r"(r[0]), "=r"(r[1]), "=r"(r[2]), "=r"(r[3]) : "r"(addr));
}
__device__ __forceinline__ void ldsm_x2(uint32_t* r, uint32_t addr) {
    asm volatile("ldmatrix.sync.aligned.m8n8.x2.shared.b16 {%0,%1}, [%2];"
        : "=r"(r[0]), "=r"(r[1]) : "r"(addr));
}
__device__ __forceinline__ void mma_bf16(float* c, const uint32_t* a, const uint32_t* b) {
    asm volatile("mma.sync.aligned.m16n8k16.row.col.f32.bf16.bf16.f32 "
        "{%0,%1,%2,%3}, {%4,%5,%6,%7}, {%8,%9}, {%0,%1,%2,%3};"
        : "+f"(c[0]), "+f"(c[1]), "+f"(c[2]), "+f"(c[3])
        : "r"(a[0]), "r"(a[1]), "r"(a[2]), "r"(a[3]), "r"(b[0]), "r"(b[1]));
}
__device__ __forceinline__ void split_bf16(float v, __nv_bfloat16& h, __nv_bfloat16& l) {
    h = __float2bfloat16_rn(v);
    l = __float2bfloat16_rn(v - __bfloat162float(h));
}

// ============================================================================
// split-bf16 tensor GEMM, 3-stage cp.async pipeline
// ============================================================================
__global__ void __launch_bounds__(256)
mma_gemm(const __nv_bfloat16* __restrict__ Ah, const __nv_bfloat16* __restrict__ Al,
         const __nv_bfloat16* __restrict__ Bh, const __nv_bfloat16* __restrict__ Bl,
         float* __restrict__ C, int M, int N, int K) {
    extern __shared__ char smem[];
    uint32_t sbase = smem_to_u32(smem);
    int tid = threadIdx.x, wid = tid >> 5, lane = tid & 31;
    int m0 = blockIdx.y * 128, n0 = blockIdx.x * 128;
    int wm = wid & 3, wn = wid >> 2;

    float acc[2][8][4];
    #pragma unroll
    for (int mt = 0; mt < 2; mt++)
        #pragma unroll
        for (int nt = 0; nt < 8; nt++)
            #pragma unroll
            for (int q = 0; q < 4; q++) acc[mt][nt][q] = 0.f;

    const int KT = K >> 6;
    int lrow = tid >> 3, lc8 = tid & 7;

    auto issue = [&](int kt) {
        uint32_t so = (uint32_t)(kt % 3) * 65536u;
        #pragma unroll
        for (int u = 0; u < 4; u++) {
            int row = lrow + 32 * u;
            uint32_t sw = swz((uint32_t)row * 128 + lc8 * 16);
            size_t aoff = ((size_t)(m0 + row) * K + kt * 64 + lc8 * 8);
            size_t boff = ((size_t)(n0 + row) * K + kt * 64 + lc8 * 8);
            cp_async16(sbase + so + sw,         Ah + aoff);
            cp_async16(sbase + so + 16384 + sw, Al + aoff);
            cp_async16(sbase + so + 32768 + sw, Bh + boff);
            cp_async16(sbase + so + 49152 + sw, Bl + boff);
        }
        CP_COMMIT();
    };

    issue(0);
    if (KT > 1) issue(1);

    for (int kt = 0; kt < KT; kt++) {
        if (kt + 1 < KT) CP_WAIT(1); else CP_WAIT(0);
        __syncthreads();
        if (kt + 2 < KT) issue(kt + 2);

        uint32_t so = (uint32_t)(kt % 3) * 65536u;
        #pragma unroll
        for (int ks = 0; ks < 4; ks++) {
            uint32_t ah[2][4], alr[2][4];
            #pragma unroll
            for (int mt = 0; mt < 2; mt++) {
                int row = wm * 32 + mt * 16 + (lane & 15);
                int kb  = ks * 32 + ((lane >> 4) << 4);
                uint32_t off = swz((uint32_t)row * 128 + kb);
                ldsm_x4(ah[mt],  sbase + so + off);
                ldsm_x4(alr[mt], sbase + so + 16384 + off);
            }
            int l2 = lane & 15;
            int nrow = wn * 64 + (l2 & 7);
            int kb2  = ks * 32 + ((l2 >> 3) << 4);
            #pragma unroll
            for (int nt = 0; nt < 8; nt++) {
                uint32_t bh[2], bl[2];
                uint32_t off = swz((uint32_t)(nrow + nt * 8) * 128 + kb2);
                ldsm_x2(bh, sbase + so + 32768 + off);
                ldsm_x2(bl, sbase + so + 49152 + off);
                #pragma unroll
                for (int mt = 0; mt < 2; mt++) {
                    mma_bf16(acc[mt][nt], ah[mt],  bh);
                    mma_bf16(acc[mt][nt], ah[mt],  bl);
                    mma_bf16(acc[mt][nt], alr[mt], bh);
                }
            }
        }
    }

    int r_base = m0 + wm * 32 + (lane >> 2);
    int c_base = n0 + wn * 64 + 2 * (lane & 3);
    #pragma unroll
    for (int mt = 0; mt < 2; mt++) {
        #pragma unroll
        for (int nt = 0; nt < 8; nt++) {
            int c = c_base + nt * 8;
            if (c < N) {
                int r = r_base + mt * 16;
                *(float2*)&C[(size_t)r * N + c]       = make_float2(acc[mt][nt][0], acc[mt][nt][1]);
                *(float2*)&C[(size_t)(r + 8) * N + c] = make_float2(acc[mt][nt][2], acc[mt][nt][3]);
            }
        }
    }
}

// ============================================================================
// weight conversion
// ============================================================================
__global__ void cvt_split_pad(const float* __restrict__ src,
                              __nv_bfloat16* __restrict__ hi,
                              __nv_bfloat16* __restrict__ lo,
                              int N, int K, int Npad) {
    size_t i = (size_t)blockIdx.x * 256 + threadIdx.x;
    if (i >= (size_t)Npad * K) return;
    int n = (int)(i / K);
    float v = (n < N) ? src[i] : 0.f;
    __nv_bfloat16 h, l; split_bf16(v, h, l);
    hi[i] = h; lo[i] = l;
}

// ============================================================================
// 1. Downsample conv -> split-bf16 A for in_proj
// ============================================================================
__global__ void downsample_kernel(const float* __restrict__ left,
                                  const float* __restrict__ right,
                                  const float* __restrict__ dw,
                                  const float* __restrict__ db) {
    extern __shared__ float sm[];
    float* sw = sm;
    float* sp = sm + DMODEL*48;
    int bi = blockIdx.x;
    int wt = bi % (WO/16);
    int oh = (bi / (WO/16)) % HO;
    int b  = (bi / (WO/16 * HO)) % B_;
    int s  = bi / (WO/16 * HO * B_);
    const float* img = s ? right : left;
    int tid = threadIdx.x;
    for (int i = tid; i < DMODEL*48; i += 256) sw[i] = dw[i];
    int ow0 = wt * 16;
    for (int i = tid; i < 16*48; i += 256) {
        int pos = i / 48, j = i % 48;
        int ci = j / 16, kh = (j % 16) / 4, kw = j % 4;
        sp[i] = img[((size_t)(b*3 + ci)*HIMG + (oh*4 + kh))*WIMG + (ow0 + pos)*4 + kw];
    }
    __syncthreads();
    int c = tid;
    float bias = db[c];
    for (int pos = 0; pos < 16; pos++) {
        float acc = bias;
        #pragma unroll
        for (int j = 0; j < 48; j++) acc += sp[pos*48 + j] * sw[c*48 + j];
        int l = oh*WO + ow0 + pos;
        size_t off = ((size_t)(s*B_ + b)*L_ + l)*DMODEL + c;
        __nv_bfloat16 h, lo; split_bf16(acc, h, lo);
        g_ah[off] = h;
        g_al[off] = lo;
    }
}

// ============================================================================
// 3. conv1d + silu, stream 0 only, sliding window (8 l-positions / thread)
// ============================================================================
__global__ void conv_split_kernel_v2(const float* __restrict__ cw,
                                     const float* __restrict__ cb) {
    int idx = blockIdx.x * 256 + threadIdx.x;
    const int NC4 = CONVD/4;         // 160
    int c4 = idx % NC4;
    int t  = idx / NC4;              // (sb, l-tile)
    if (t >= B_ * (L_/8)) return;
    int lt = t % (L_/8);
    int sb = t / (L_/8);
    int l0 = lt * 8;
    int ch = c4 * 4;

    float4 w0 = *(const float4*)&cw[(ch+0)*4];
    float4 w1 = *(const float4*)&cw[(ch+1)*4];
    float4 w2 = *(const float4*)&cw[(ch+2)*4];
    float4 w3 = *(const float4*)&cw[(ch+3)*4];
    float4 bias = *(const float4*)&cb[ch];

    float4 v[11];
    #pragma unroll
    for (int r = 0; r < 11; r++) {
        int ls = l0 - 3 + r;
        v[r] = (ls >= 0) ? *(const float4*)&g_zx[((size_t)sb*L_ + ls)*DPROJ + 512 + ch]
                         : make_float4(0.f, 0.f, 0.f, 0.f);
    }

    #pragma unroll
    for (int i = 0; i < 8; i++) {
        float a0 = bias.x + w0.x*v[i].x + w0.y*v[i+1].x + w0.z*v[i+2].x + w0.w*v[i+3].x;
        float a1 = bias.y + w1.x*v[i].y + w1.y*v[i+1].y + w1.z*v[i+2].y + w1.w*v[i+3].y;
        float a2 = bias.z + w2.x*v[i].z + w2.y*v[i+1].z + w2.z*v[i+2].z + w2.w*v[i+3].z;
        float a3 = bias.w + w3.x*v[i].w + w3.y*v[i+1].w + w3.z*v[i+2].w + w3.w*v[i+3].w;
        float4 out;
        out.x = a0 / (1.f + __expf(-a0));
        out.y = a1 / (1.f + __expf(-a1));
        out.z = a2 / (1.f + __expf(-a2));
        out.w = a3 / (1.f + __expf(-a3));
        *(float4*)&g_xbc[((size_t)sb*L_ + l0 + i)*CONVD + ch] = out;
    }
}

// ============================================================================
// 4. dt softplus
// ============================================================================
__global__ void dt_kernel(const float* __restrict__ dt_bias) {
    size_t idx = (size_t)blockIdx.x * 256 + threadIdx.x;
    if (idx >= (size_t)2*B_*L_*NH) return;
    int h = (int)(idx % NH);
    size_t row = idx / NH;
    float v = g_zx[row*DPROJ + (DINNER + CONVD) + h] + dt_bias[h];
    g_dt[idx] = (v > 20.f) ? v : log1pf(__expf(v));
}

// ============================================================================
// 5. per-chunk cumsum (warp-parallel)
// ============================================================================
__global__ void cum_kernel_v2(const float* __restrict__ A_log) {
    int gw = blockIdx.x * 8 + (threadIdx.x >> 5);
    int lane = threadIdx.x & 31;
    if (gw >= 2*B_*NC*NH) return;
    int h = gw % NH;
    int c = (gw / NH) % NC;
    int sb = gw / (NH * NC);
    float An = -__expf(A_log[h]);
    size_t base = ((size_t)sb*L_ + c*CHUNKSZ + lane*4)*NH + h;
    float v0 = g_dt[base], v1 = g_dt[base + NH], v2 = g_dt[base + 2*NH], v3 = g_dt[base + 3*NH];
    float p0 = v0, p1 = p0 + v1, p2 = p1 + v2, p3 = p2 + v3;
    float incl = p3;
    #pragma unroll
    for (int o = 1; o < 32; o <<= 1) {
        float t = __shfl_up_sync(0xFFFFFFFFu, incl, o);
        if (lane >= o) incl += t;
    }
    float ex = incl - p3;
    g_cum[base]        = An * (ex + p0);
    g_cum[base + NH]   = An * (ex + p1);
    g_cum[base + 2*NH] = An * (ex + p2);
    g_cum[base + 3*NH] = An * (ex + p3);
}

// ============================================================================
// 6. Intra-chunk SSD via tensor cores
// ============================================================================
#define CK_XT_H(p) (2048u + (uint32_t)(p)*16384u)
#define CK_XT_L(p) (34816u + (uint32_t)(p)*16384u)
#define CK_BW_H(p) (67584u + (uint32_t)(p)*8192u)
#define CK_BW_L(p) (83968u + (uint32_t)(p)*8192u)
#define CK_R1      100352u
#define CK_GH(p)   (CK_R1 + (uint32_t)(p)*16384u)
#define CK_GL(p)   (CK_R1 + 32768u + (uint32_t)(p)*16384u)
#define CK_SMEM    165888

__global__ void __launch_bounds__(256)
chunk_kernel_v2(const float* __restrict__ Dv) {
    extern __shared__ char smraw[];
    uint32_t sbase = smem_to_u32(smraw);
    float* cum_s = (float*)smraw;
    float* dts_s = (float*)(smraw + 512);
    float* wj_s  = (float*)(smraw + 1024);

    int bi = blockIdx.x, tid = threadIdx.x;
    int wid = tid >> 5, lane = tid & 31;
    int wm = wid & 3, wn = wid >> 2;
    int l2 = lane & 15;
    int h  = bi % NH;
    int c  = (bi / NH) % NC;
    int b  = (bi / (NH*NC)) % B_;
    int s  = bi / (NH*NC*B_);
    int sb  = s*B_ + b;
    int sbo = (1 - s)*B_ + b;
    size_t l0 = (size_t)c * CHUNKSZ;

    if (tid < 128) {
        size_t off = ((size_t)sb*L_ + l0 + tid)*NH + h;
        cum_s[tid] = g_cum[off];
        dts_s[tid] = g_dt[off];
    }
    __syncthreads();
    if (tid < 128) wj_s[tid] = dts_s[tid] * __expf(cum_s[127] - cum_s[tid]);
    __syncthreads();

    for (int idx = tid; idx < 128*64; idx += 256) {
        int j = idx >> 6, n = idx & 63;
        float cv = xbc_row(sb,  l0 + j)[576 + n];
        float bv = xbc_row(sbo, l0 + j)[512 + n];
        __nv_bfloat16 hh, ll;
        uint32_t so = swz((uint32_t)j*128 + n*2);
        split_bf16(cv, hh, ll);
        *(__nv_bfloat16*)(smraw + CK_R1 + so)         = hh;
        *(__nv_bfloat16*)(smraw + CK_R1 + 16384 + so) = ll;
        split_bf16(bv, hh, ll);
        *(__nv_bfloat16*)(smraw + CK_R1 + 32768 + so) = hh;
        *(__nv_bfloat16*)(smraw + CK_R1 + 49152 + so) = ll;
        float bw = bv * wj_s[j];
        split_bf16(bw, hh, ll);
        uint32_t st = swz((uint32_t)n*128 + (j & 63)*2);
        int pan = j >> 6;
        *(__nv_bfloat16*)(smraw + CK_BW_H(pan) + st) = hh;
        *(__nv_bfloat16*)(smraw + CK_BW_L(pan) + st) = ll;
    }
    for (int idx = tid; idx < 128*128; idx += 256) {
        int j = idx >> 7, p = idx & 127;
        float xv = xbc_row(sbo, l0 + j)[h*HD + p];
        __nv_bfloat16 hh, ll; split_bf16(xv, hh, ll);
        int pan = j >> 6;
        uint32_t st = swz((uint32_t)p*128 + (j & 63)*2);
        *(__nv_bfloat16*)(smraw + CK_XT_H(pan) + st) = hh;
        *(__nv_bfloat16*)(smraw + CK_XT_L(pan) + st) = ll;
    }
    __syncthreads();

    // phase A: G = C * B^T
    float accg[2][8][4];
    #pragma unroll
    for (int mt = 0; mt < 2; mt++)
        #pragma unroll
        for (int nt = 0; nt < 8; nt++)
            #pragma unroll
            for (int q = 0; q < 4; q++) accg[mt][nt][q] = 0.f;
    #pragma unroll
    for (int ks = 0; ks < 4; ks++) {
        uint32_t ah[2][4], al[2][4];
        #pragma unroll
        for (int mt = 0; mt < 2; mt++) {
            int row = wm*32 + mt*16 + (lane & 15);
            uint32_t off = swz((uint32_t)row*128 + ks*32 + ((lane >> 4) << 4));
            ldsm_x4(ah[mt], sbase + CK_R1 + off);
            ldsm_x4(al[mt], sbase + CK_R1 + 16384 + off);
        }
        #pragma unroll
        for (int nt = 0; nt < 8; nt++) {
            int row = wn*64 + nt*8 + (l2 & 7);
            uint32_t off = swz((uint32_t)row*128 + ks*32 + ((l2 >> 3) << 4));
            uint32_t bh[2], bl[2];
            ldsm_x2(bh, sbase + CK_R1 + 32768 + off);
            ldsm_x2(bl, sbase + CK_R1 + 49152 + off);
            #pragma unroll
            for (int mt = 0; mt < 2; mt++) {
                mma_bf16(accg[mt][nt], ah[mt], bh);
                mma_bf16(accg[mt][nt], ah[mt], bl);
                mma_bf16(accg[mt][nt], al[mt], bh);
            }
        }
    }
    __syncthreads();

    {
        int r0 = lane >> 2, cj = 2*(lane & 3);
        #pragma unroll
        for (int mt = 0; mt < 2; mt++) {
            #pragma unroll
            for (int nt = 0; nt < 8; nt++) {
                int j0 = wn*64 + nt*8 + cj;
                int jl = (j0 & 63);
                #pragma unroll
                for (int half = 0; half < 2; half++) {
                    int i = wm*32 + mt*16 + r0 + half*8;
                    float ci = cum_s[i];
                    float g0 = (j0   <= i) ? accg[mt][nt][half*2]   * __expf(ci - cum_s[j0])   * dts_s[j0]   : 0.f;
                    float g1 = (j0+1 <= i) ? accg[mt][nt][half*2+1] * __expf(ci - cum_s[j0+1]) * dts_s[j0+1] : 0.f;
                    __nv_bfloat16 h0, l0b, h1, l1b;
                    split_bf16(g0, h0, l0b); split_bf16(g1, h1, l1b);
                    uint32_t st = swz((uint32_t)i*128 + jl*2);
                    *(__nv_bfloat162*)(smraw + CK_GH(wn) + st) = __nv_bfloat162(h0, h1);
                    *(__nv_bfloat162*)(smraw + CK_GL(wn) + st) = __nv_bfloat162(l0b, l1b);
                }
            }
        }
    }
    __syncthreads();

    // phase B: Y = G @ X
    {
        float accy[2][8][4];
        #pragma unroll
        for (int mt = 0; mt < 2; mt++)
            #pragma unroll
            for (int nt = 0; nt < 8; nt++)
                #pragma unroll
                for (int q = 0; q < 4; q++) accy[mt][nt][q] = 0.f;
        #pragma unroll
        for (int pan = 0; pan < 2; pan++) {
            #pragma unroll
            for (int ks = 0; ks < 4; ks++) {
                uint32_t gh[2][4], gl[2][4];
                #pragma unroll
                for (int mt = 0; mt < 2; mt++) {
                    int row = wm*32 + mt*16 + (lane & 15);
                    uint32_t off = swz((uint32_t)row*128 + ks*32 + ((lane >> 4) << 4));
                    ldsm_x4(gh[mt], sbase + CK_GH(pan) + off);
                    ldsm_x4(gl[mt], sbase + CK_GL(pan) + off);
                }
                #pragma unroll
                for (int nt = 0; nt < 8; nt++) {
                    int row = wn*64 + nt*8 + (l2 & 7);
                    uint32_t off = swz((uint32_t)row*128 + ks*32 + ((l2 >> 3) << 4));
                    uint32_t xh[2], xl[2];
                    ldsm_x2(xh, sbase + CK_XT_H(pan) + off);
                    ldsm_x2(xl, sbase + CK_XT_L(pan) + off);
                    #pragma unroll
                    for (int mt = 0; mt < 2; mt++) {
                        mma_bf16(accy[mt][nt], gh[mt], xh);
                        mma_bf16(accy[mt][nt], gh[mt], xl);
                        mma_bf16(accy[mt][nt], gl[mt], xh);
                    }
                }
            }
        }
        float Dh = Dv[h];
        int r0 = lane >> 2, cp = 2*(lane & 3);
        #pragma unroll
        for (int mt = 0; mt < 2; mt++) {
            #pragma unroll
            for (int nt = 0; nt < 8; nt++) {
                int p0 = wn*64 + nt*8 + cp;
                #pragma unroll
                for (int half = 0; half < 2; half++) {
                    int i = wm*32 + mt*16 + r0 + half*8;
                    int ipan = i >> 6;
                    uint32_t b0 = swz((uint32_t)p0*128 + (i & 63)*2);
                    uint32_t b1 = swz((uint32_t)(p0+1)*128 + (i & 63)*2);
                    float x0 = __bfloat162float(*(__nv_bfloat16*)(smraw + CK_XT_H(ipan) + b0))
                             + __bfloat162float(*(__nv_bfloat16*)(smraw + CK_XT_L(ipan) + b0));
                    float x1 = __bfloat162float(*(__nv_bfloat16*)(smraw + CK_XT_H(ipan) + b1))
                             + __bfloat162float(*(__nv_bfloat16*)(smraw + CK_XT_L(ipan) + b1));
                    size_t off = ((size_t)sb*L_ + l0 + i)*DINNER + h*HD + p0;
                    *(float2*)&g_y[off] = make_float2(accy[mt][nt][half*2] + Dh*x0,
                                                      accy[mt][nt][half*2+1] + Dh*x1);
                }
            }
        }
    }

    // phase C: S = X^T @ Bw
    {
        float accs[2][4][4];
        #pragma unroll
        for (int mt = 0; mt < 2; mt++)
            #pragma unroll
            for (int nt = 0; nt < 4; nt++)
                #pragma unroll
                for (int q = 0; q < 4; q++) accs[mt][nt][q] = 0.f;
        #pragma unroll
        for (int pan = 0; pan < 2; pan++) {
            #pragma unroll
            for (int ks = 0; ks < 4; ks++) {
                uint32_t xh[2][4], xl[2][4];
                #pragma unroll
                for (int mt = 0; mt < 2; mt++) {
                    int row = wm*32 + mt*16 + (lane & 15);
                    uint32_t off = swz((uint32_t)row*128 + ks*32 + ((lane >> 4) << 4));
                    ldsm_x4(xh[mt], sbase + CK_XT_H(pan) + off);
                    ldsm_x4(xl[mt], sbase + CK_XT_L(pan) + off);
                }
                #pragma unroll
                for (int nt = 0; nt < 4; nt++) {
                    int row = wn*32 + nt*8 + (l2 & 7);
                    uint32_t off = swz((uint32_t)row*128 + ks*32 + ((l2 >> 3) << 4));
                    uint32_t bwh[2], bwl[2];
                    ldsm_x2(bwh, sbase + CK_BW_H(pan) + off);
                    ldsm_x2(bwl, sbase + CK_BW_L(pan) + off);
                    #pragma unroll
                    for (int mt = 0; mt < 2; mt++) {
                        mma_bf16(accs[mt][nt], xh[mt], bwh);
                        mma_bf16(accs[mt][nt], xh[mt], bwl);
                        mma_bf16(accs[mt][nt], xl[mt], bwh);
                    }
                }
            }
        }
        size_t sb0 = (size_t)bi * (HD*DSTATE);
        int r0 = lane >> 2, cn = 2*(lane & 3);
        #pragma unroll
        for (int mt = 0; mt < 2; mt++) {
            #pragma unroll
            for (int nt = 0; nt < 4; nt++) {
                int n0 = wn*32 + nt*8 + cn;
                #pragma unroll
                for (int half = 0; half < 2; half++) {
                    int p = wm*32 + mt*16 + r0 + half*8;
                    *(float2*)&g_state[sb0 + (size_t)p*64 + n0] =
                        make_float2(accs[mt][nt][half*2], accs[mt][nt][half*2+1]);
                }
            }
        }
    }
}

// ============================================================================
// 7. Inter-chunk scan
// ============================================================================
__global__ void scan_kernel_v2() {
    int t   = blockIdx.x >> 3;
    int seg = blockIdx.x & 7;
    int h = t % NH;
    int sb = t / NH;
    int off0 = seg * 1024 + threadIdx.x * 4;
    float4 hreg = make_float4(0.f, 0.f, 0.f, 0.f);
    for (int c = 0; c < NC; c++) {
        float dec = __expf(g_cum[((size_t)sb*L_ + c*CHUNKSZ + 127)*NH + h]);
        size_t o = (((size_t)sb*NC + c)*NH + h) * (HD*DSTATE) + off0;
        *(float4*)&g_hprev[o] = hreg;
        float4 st = *(const float4*)&g_state[o];
        hreg.x = hreg.x*dec + st.x;
        hreg.y = hreg.y*dec + st.y;
        hreg.z = hreg.z*dec + st.z;
        hreg.w = hreg.w*dec + st.w;
    }
}

// ============================================================================
// 8. Inter-chunk contribution via tensor cores
// ============================================================================
__global__ void __launch_bounds__(256)
interchunk_kernel_v2() {
    extern __shared__ char smraw[];
    uint32_t sbase = smem_to_u32(smraw);
    float* cum_s = (float*)smraw;

    int bi = blockIdx.x, tid = threadIdx.x;
    int wid = tid >> 5, lane = tid & 31;
    int wm = wid & 3, wn = wid >> 2;
    int l2 = lane & 15;
    int h  = bi % NH;
    int c  = (bi / NH) % NC;
    int b  = (bi / (NH*NC)) % B_;
    int s  = bi / (NH*NC*B_);
    int sb = s*B_ + b;
    size_t l0 = (size_t)c * CHUNKSZ;
    size_t hbase = (size_t)bi * (HD*DSTATE);

    if (tid < 128) cum_s[tid] = g_cum[((size_t)sb*L_ + l0 + tid)*NH + h];

    for (int idx = tid; idx < 128*64; idx += 256) {
        int r = idx >> 6, n = idx & 63;
        float cv = xbc_row(sb, l0 + r)[576 + n];
        float hv = g_hprev[hbase + idx];
        __nv_bfloat16 hh, ll;
        uint32_t so = swz((uint32_t)r*128 + n*2);
        split_bf16(cv, hh, ll);
        *(__nv_bfloat16*)(smraw + 1024 + so)         = hh;
        *(__nv_bfloat16*)(smraw + 1024 + 16384 + so) = ll;
        split_bf16(hv, hh, ll);
        *(__nv_bfloat16*)(smraw + 1024 + 32768 + so) = hh;
        *(__nv_bfloat16*)(smraw + 1024 + 49152 + so) = ll;
    }
    __syncthreads();

    float acc[2][8][4];
    #pragma unroll
    for (int mt = 0; mt < 2; mt++)
        #pragma unroll
        for (int nt = 0; nt < 8; nt++)
            #pragma unroll
            for (int q = 0; q < 4; q++) acc[mt][nt][q] = 0.f;
    #pragma unroll
    for (int ks = 0; ks < 4; ks++) {
        uint32_t ah[2][4], al[2][4];
        #pragma unroll
        for (int mt = 0; mt < 2; mt++) {
            int row = wm*32 + mt*16 + (lane & 15);
            uint32_t off = swz((uint32_t)row*128 + ks*32 + ((lane >> 4) << 4));
            ldsm_x4(ah[mt], sbase + 1024 + off);
            ldsm_x4(al[mt], sbase + 1024 + 16384 + off);
        }
        #pragma unroll
        for (int nt = 0; nt < 8; nt++) {
            int row = wn*64 + nt*8 + (l2 & 7);
            uint32_t off = swz((uint32_t)row*128 + ks*32 + ((l2 >> 3) << 4));
            uint32_t hh[2], hl[2];
            ldsm_x2(hh, sbase + 1024 + 32768 + off);
            ldsm_x2(hl, sbase + 1024 + 49152 + off);
            #pragma unroll
            for (int mt = 0; mt < 2; mt++) {
                mma_bf16(acc[mt][nt], ah[mt], hh);
                mma_bf16(acc[mt][nt], ah[mt], hl);
                mma_bf16(acc[mt][nt], al[mt], hh);
            }
        }
    }

    int r0 = lane >> 2, cp = 2*(lane & 3);
    #pragma unroll
    for (int mt = 0; mt < 2; mt++) {
        #pragma unroll
        for (int nt = 0; nt < 8; nt++) {
            int p = wn*64 + nt*8 + cp;
            #pragma unroll
            for (int half = 0; half < 2; half++) {
                int i = wm*32 + mt*16 + r0 + half*8;
                float sc = __expf(cum_s[i]);
                size_t off = ((size_t)sb*L_ + l0 + i)*DINNER + h*HD + p;
                float2 v = *(float2*)&g_y[off];
                v.x += sc * acc[mt][nt][half*2];
                v.y += sc * acc[mt][nt][half*2+1];
                *(float2*)&g_y[off] = v;
            }
        }
    }
}

// ============================================================================
// 9. Gated RMSNorm -> split-bf16 A for out_proj
// ============================================================================
__global__ void rmsnorm_kernel(const float* __restrict__ norm_w) {
    int row = blockIdx.x;
    int tid = threadIdx.x;
    __shared__ float red[4];
    size_t ybase = (size_t)row * DINNER;
    size_t zbase = (size_t)row * DPROJ;
    float g[4];
    float ss = 0.f;
    #pragma unroll
    for (int t = 0; t < 4; t++) {
        int d = tid + 128*t;
        float z = g_zx[zbase + d];
        float yv = g_y[ybase + d];
        float gg = yv * (z / (1.f + __expf(-z)));
        g[t] = gg;
        ss += gg*gg;
    }
    #pragma unroll
    for (int o = 16; o > 0; o >>= 1) ss += __shfl_xor_sync(0xFFFFFFFFu, ss, o);
    if ((tid & 31) == 0) red[tid >> 5] = ss;
    __syncthreads();
    float tot = red[0] + red[1] + red[2] + red[3];
    float scale = rsqrtf(tot / (float)DINNER + 1e-5f);
    #pragma unroll
    for (int t = 0; t < 4; t++) {
        int d = tid + 128*t;
        float v = g[t] * scale * norm_w[d];
        __nv_bfloat16 h, l; split_bf16(v, h, l);
        g_ah[ybase + d] = h;
        g_al[ybase + d] = l;
    }
}

// ============================================================================
extern "C" void kernel_launch(void* const* d_in, const int* in_sizes, int n_in,
                              void* d_out, int out_size) {
    const float* left   = (const float*)d_in[0];
    const float* right  = (const float*)d_in[1];
    const float* dw     = (const float*)d_in[2];
    const float* db     = (const float*)d_in[3];
    const float* inpw   = (const float*)d_in[4];
    const float* cw     = (const float*)d_in[5];
    const float* cb     = (const float*)d_in[6];
    const float* dtb    = (const float*)d_in[7];
    const float* alog   = (const float*)d_in[8];
    const float* Dv     = (const float*)d_in[9];
    const float* nw     = (const float*)d_in[10];
    const float* outw   = (const float*)d_in[11];
    float* out          = (float*)d_out;

    float *p_zx;
    __nv_bfloat16 *p_ah, *p_al, *p_bh, *p_bl;
    cudaGetSymbolAddress((void**)&p_zx, g_zx);
    cudaGetSymbolAddress((void**)&p_ah, g_ah);
    cudaGetSymbolAddress((void**)&p_al, g_al);
    cudaGetSymbolAddress((void**)&p_bh, g_bh);
    cudaGetSymbolAddress((void**)&p_bl, g_bl);

    const int ds_smem  = (DMODEL*48 + 16*48) * 4;
    const int mma_smem = 3 * 65536;
    const int ic_smem  = 66560;
    cudaFuncSetAttribute(downsample_kernel,    cudaFuncAttributeMaxDynamicSharedMemorySize, ds_smem);
    cudaFuncSetAttribute(mma_gemm,             cudaFuncAttributeMaxDynamicSharedMemorySize, mma_smem);
    cudaFuncSetAttribute(chunk_kernel_v2,      cudaFuncAttributeMaxDynamicSharedMemorySize, CK_SMEM);
    cudaFuncSetAttribute(interchunk_kernel_v2, cudaFuncAttributeMaxDynamicSharedMemorySize, ic_smem);

    const int M = 2*B_*L_;   // 65536

    // 1. downsample
    downsample_kernel<<<2*B_*HO*(WO/16), 256, ds_smem>>>(left, right, dw, db);

    // 2. in_proj
    {
        size_t nb = (size_t)DPROJ_PAD * DMODEL;
        cvt_split_pad<<<(unsigned)((nb + 255)/256), 256>>>(inpw, p_bh, p_bl, DPROJ, DMODEL, DPROJ_PAD);
        dim3 grid(DPROJ_PAD/128, M/128);
        mma_gemm<<<grid, 256, mma_smem>>>(p_ah, p_al, p_bh, p_bl, p_zx, M, DPROJ, DMODEL);
    }

    // 3. conv+silu (stream 0 only; stream 1 read raw from g_zx downstream)
    {
        int total = B_ * (L_/8) * (CONVD/4);
        conv_split_kernel_v2<<<(total + 255)/256, 256>>>(cw, cb);
    }
    {
        size_t tot = (size_t)M*NH;
        dt_kernel<<<(unsigned)((tot + 255)/256), 256>>>(dtb);
    }
    cum_kernel_v2<<<2*B_*NC*NH/8, 256>>>(alog);

    // 6-8. SSD
    chunk_kernel_v2<<<2*B_*NC*NH, 256, CK_SMEM>>>(Dv);
    scan_kernel_v2<<<2*B_*NH*8, 256>>>();
    interchunk_kernel_v2<<<2*B_*NC*NH, 256, ic_smem>>>();

    // 9. rmsnorm
    rmsnorm_kernel<<<M, 128>>>(nw);

    // 10. out_proj
    {
        size_t nb = (size_t)DMODEL * DINNER;
        cvt_split_pad<<<(unsigned)((nb + 255)/256), 256>>>(outw, p_bh, p_bl, DMODEL, DINNER, DMODEL);
        dim3 grid(DMODEL/128, M/128);
        mma_gemm<<<grid, 256, mma_smem>>>(p_ah, p_al, p_bh, p_bl, out, M, DMODEL, DINNER);
    }
}

// round 17
// speedup vs baseline: 1.1323x; 1.0955x over previous
#include <cuda_runtime.h>
#include <cuda_bf16.h>
#include <cuda_fp16.h>
#include <math.h>
#include <stdint.h>

// ---------------- problem constants ----------------
#define B_      4
#define L_      8192
#define DMODEL  256
#define DINNER  512
#define DSTATE  64
#define NH      4
#define HD      128
#define CHUNKSZ 128
#define NC      64
#define CONVD   640
#define DPROJ   1156
#define DPROJ_PAD 1280
#define HIMG    256
#define WIMG    512
#define HO      64
#define WO      128

// ---------------- static scratch ----------------
__device__ float g_zx   [(size_t)2*B_*L_*DPROJ];
__device__ float g_xbc  [(size_t)B_*L_*CONVD];     // stream 0 only (conv+silu)
__device__ float g_dt   [(size_t)2*B_*L_*NH];
__device__ float g_cum  [(size_t)2*B_*L_*NH];
__device__ float g_y    [(size_t)2*B_*L_*DINNER];
__device__ float g_state[(size_t)2*B_*NC*NH*HD*DSTATE];
__device__ float g_hprev[(size_t)2*B_*NC*NH*HD*DSTATE];
__device__ __half g_a16 [(size_t)2*B_*L_*DINNER];          // fp16 A operand
__device__ __half g_bh  [(size_t)DPROJ_PAD*DMODEL];        // fp16 weight hi
__device__ __half g_bl  [(size_t)DPROJ_PAD*DMODEL];        // fp16 weight lo

// xBC row accessor: stream 0 lives in g_xbc (post conv+silu);
// stream 1 is the raw in_proj slice, read straight from g_zx.
__device__ __forceinline__ const float* xbc_row(int sbb, size_t l) {
    return (sbb < B_) ? &g_xbc[((size_t)sbb*L_ + l)*CONVD]
                      : &g_zx [((size_t)sbb*L_ + l)*DPROJ + 512];
}

// ---------------- mma.sync helpers ----------------
__device__ __forceinline__ uint32_t smem_to_u32(const void* p) {
    uint32_t a;
    asm("{ .reg .u64 t; cvta.to.shared.u64 t, %1; cvt.u32.u64 %0, t; }" : "=r"(a) : "l"(p));
    return a;
}
__device__ __forceinline__ uint32_t swz(uint32_t o) { return o ^ ((o >> 3) & 0x70); }

__device__ __forceinline__ void cp_async16(uint32_t saddr, const void* gptr) {
    asm volatile("cp.async.cg.shared.global [%0], [%1], 16;" :: "r"(saddr), "l"(gptr));
}
#define CP_COMMIT() asm volatile("cp.async.commit_group;" ::: "memory")
#define CP_WAIT(n)  asm volatile("cp.async.wait_group %0;" :: "n"(n) : "memory")

__device__ __forceinline__ void ldsm_x4(uint32_t* r, uint32_t addr) {
    asm volatile("ldmatrix.sync.aligned.m8n8.x4.shared.b16 {%0,%1,%2,%3}, [%4];"
        : "=r"(r[0]), "=r"(r[1]), "=r"(r[2]), "=r"(r[3]) : "r"(addr));
}
__device__ __forceinline__ void ldsm_x2(uint32_t* r, uint32_t addr) {
    asm volatile("ldmatrix.sync.aligned.m8n8.x2.shared.b16 {%0,%1}, [%2];"
        : "=r"(r[0]), "=r"(r[1]) : "r"(addr));
}
__device__ __forceinline__ void mma_bf16(float* c, const uint32_t* a, const uint32_t* b) {
    asm volatile("mma.sync.aligned.m16n8k16.row.col.f32.bf16.bf16.f32 "
        "{%0,%1,%2,%3}, {%4,%5,%6,%7}, {%8,%9}, {%0,%1,%2,%3};"
        : "+f"(c[0]), "+f"(c[1]), "+f"(c[2]), "+f"(c[3])
        : "r"(a[0]), "r"(a[1]), "r"(a[2]), "r"(a[3]), "r"(b[0]), "r"(b[1]));
}
__device__ __forceinline__ void mma_f16(float* c, const uint32_t* a, const uint32_t* b) {
    asm volatile("mma.sync.aligned.m16n8k16.row.col.f32.f16.f16.f32 "
        "{%0,%1,%2,%3}, {%4,%5,%6,%7}, {%8,%9}, {%0,%1,%2,%3};"
        : "+f"(c[0]), "+f"(c[1]), "+f"(c[2]), "+f"(c[3])
        : "r"(a[0]), "r"(a[1]), "r"(a[2]), "r"(a[3]), "r"(b[0]), "r"(b[1]));
}
__device__ __forceinline__ void split_bf16(float v, __nv_bfloat16& h, __nv_bfloat16& l) {
    h = __float2bfloat16_rn(v);
    l = __float2bfloat16_rn(v - __bfloat162float(h));
}
__device__ __forceinline__ void split_f16(float v, __half& h, __half& l) {
    h = __float2half_rn(v);
    l = __float2half_rn(v - __half2float(h));
}

// ============================================================================
// fp16 tensor GEMM (A plain fp16, B split-fp16, 2 MMAs/step), 3-stage pipeline.
// stage = 49152 B: A +0 (16K), Bh +16384, Bl +32768.
// ============================================================================
#define GF_STAGE 49152u
__global__ void __launch_bounds__(256)
mma_gemm(const __half* __restrict__ A16,
         const __half* __restrict__ Bh, const __half* __restrict__ Bl,
         float* __restrict__ C, int M, int N, int K) {
    extern __shared__ char smem[];
    uint32_t sbase = smem_to_u32(smem);
    int tid = threadIdx.x, wid = tid >> 5, lane = tid & 31;
    int m0 = blockIdx.y * 128, n0 = blockIdx.x * 128;
    int wm = wid & 3, wn = wid >> 2;

    float acc[2][8][4];
    #pragma unroll
    for (int mt = 0; mt < 2; mt++)
        #pragma unroll
        for (int nt = 0; nt < 8; nt++)
            #pragma unroll
            for (int q = 0; q < 4; q++) acc[mt][nt][q] = 0.f;

    const int KT = K >> 6;
    int lrow = tid >> 3, lc8 = tid & 7;

    auto issue = [&](int kt) {
        uint32_t so = (uint32_t)(kt % 3) * GF_STAGE;
        #pragma unroll
        for (int u = 0; u < 4; u++) {
            int row = lrow + 32 * u;
            uint32_t sw = swz((uint32_t)row * 128 + lc8 * 16);
            size_t aoff = ((size_t)(m0 + row) * K + kt * 64 + lc8 * 8);
            size_t boff = ((size_t)(n0 + row) * K + kt * 64 + lc8 * 8);
            cp_async16(sbase + so + sw,         A16 + aoff);
            cp_async16(sbase + so + 16384 + sw, Bh + boff);
            cp_async16(sbase + so + 32768 + sw, Bl + boff);
        }
        CP_COMMIT();
    };

    issue(0);
    if (KT > 1) issue(1);

    for (int kt = 0; kt < KT; kt++) {
        if (kt + 1 < KT) CP_WAIT(1); else CP_WAIT(0);
        __syncthreads();
        if (kt + 2 < KT) issue(kt + 2);

        uint32_t so = (uint32_t)(kt % 3) * GF_STAGE;
        #pragma unroll
        for (int ks = 0; ks < 4; ks++) {
            uint32_t ah[2][4];
            #pragma unroll
            for (int mt = 0; mt < 2; mt++) {
                int row = wm * 32 + mt * 16 + (lane & 15);
                int kb  = ks * 32 + ((lane >> 4) << 4);
                uint32_t off = swz((uint32_t)row * 128 + kb);
                ldsm_x4(ah[mt], sbase + so + off);
            }
            int l2 = lane & 15;
            int nrow = wn * 64 + (l2 & 7);
            int kb2  = ks * 32 + ((l2 >> 3) << 4);
            #pragma unroll
            for (int nt = 0; nt < 8; nt++) {
                uint32_t bh[2], bl[2];
                uint32_t off = swz((uint32_t)(nrow + nt * 8) * 128 + kb2);
                ldsm_x2(bh, sbase + so + 16384 + off);
                ldsm_x2(bl, sbase + so + 32768 + off);
                #pragma unroll
                for (int mt = 0; mt < 2; mt++) {
                    mma_f16(acc[mt][nt], ah[mt], bh);
                    mma_f16(acc[mt][nt], ah[mt], bl);
                }
            }
        }
    }

    int r_base = m0 + wm * 32 + (lane >> 2);
    int c_base = n0 + wn * 64 + 2 * (lane & 3);
    #pragma unroll
    for (int mt = 0; mt < 2; mt++) {
        #pragma unroll
        for (int nt = 0; nt < 8; nt++) {
            int c = c_base + nt * 8;
            if (c < N) {
                int r = r_base + mt * 16;
                *(float2*)&C[(size_t)r * N + c]       = make_float2(acc[mt][nt][0], acc[mt][nt][1]);
                *(float2*)&C[(size_t)(r + 8) * N + c] = make_float2(acc[mt][nt][2], acc[mt][nt][3]);
            }
        }
    }
}

// ============================================================================
// weight conversion (fp16 split, with row padding)
// ============================================================================
__global__ void cvt_split_pad(const float* __restrict__ src,
                              __half* __restrict__ hi,
                              __half* __restrict__ lo,
                              int N, int K, int Npad) {
    size_t i = (size_t)blockIdx.x * 256 + threadIdx.x;
    if (i >= (size_t)Npad * K) return;
    int n = (int)(i / K);
    float v = (n < N) ? src[i] : 0.f;
    __half h, l; split_f16(v, h, l);
    hi[i] = h; lo[i] = l;
}

// ============================================================================
// 1. Downsample conv -> fp16 A for in_proj
// ============================================================================
__global__ void downsample_kernel(const float* __restrict__ left,
                                  const float* __restrict__ right,
                                  const float* __restrict__ dw,
                                  const float* __restrict__ db) {
    extern __shared__ float sm[];
    float* sw = sm;
    float* sp = sm + DMODEL*48;
    int bi = blockIdx.x;
    int wt = bi % (WO/16);
    int oh = (bi / (WO/16)) % HO;
    int b  = (bi / (WO/16 * HO)) % B_;
    int s  = bi / (WO/16 * HO * B_);
    const float* img = s ? right : left;
    int tid = threadIdx.x;
    for (int i = tid; i < DMODEL*48; i += 256) sw[i] = dw[i];
    int ow0 = wt * 16;
    for (int i = tid; i < 16*48; i += 256) {
        int pos = i / 48, j = i % 48;
        int ci = j / 16, kh = (j % 16) / 4, kw = j % 4;
        sp[i] = img[((size_t)(b*3 + ci)*HIMG + (oh*4 + kh))*WIMG + (ow0 + pos)*4 + kw];
    }
    __syncthreads();
    int c = tid;
    float bias = db[c];
    for (int pos = 0; pos < 16; pos++) {
        float acc = bias;
        #pragma unroll
        for (int j = 0; j < 48; j++) acc += sp[pos*48 + j] * sw[c*48 + j];
        int l = oh*WO + ow0 + pos;
        size_t off = ((size_t)(s*B_ + b)*L_ + l)*DMODEL + c;
        g_a16[off] = __float2half_rn(acc);
    }
}

// ============================================================================
// 3. conv1d + silu, stream 0 only, sliding window (8 l-positions / thread)
// ============================================================================
__global__ void conv_split_kernel_v2(const float* __restrict__ cw,
                                     const float* __restrict__ cb) {
    int idx = blockIdx.x * 256 + threadIdx.x;
    const int NC4 = CONVD/4;
    int c4 = idx % NC4;
    int t  = idx / NC4;
    if (t >= B_ * (L_/8)) return;
    int lt = t % (L_/8);
    int sb = t / (L_/8);
    int l0 = lt * 8;
    int ch = c4 * 4;

    float4 w0 = *(const float4*)&cw[(ch+0)*4];
    float4 w1 = *(const float4*)&cw[(ch+1)*4];
    float4 w2 = *(const float4*)&cw[(ch+2)*4];
    float4 w3 = *(const float4*)&cw[(ch+3)*4];
    float4 bias = *(const float4*)&cb[ch];

    float4 v[11];
    #pragma unroll
    for (int r = 0; r < 11; r++) {
        int ls = l0 - 3 + r;
        v[r] = (ls >= 0) ? *(const float4*)&g_zx[((size_t)sb*L_ + ls)*DPROJ + 512 + ch]
                         : make_float4(0.f, 0.f, 0.f, 0.f);
    }

    #pragma unroll
    for (int i = 0; i < 8; i++) {
        float a0 = bias.x + w0.x*v[i].x + w0.y*v[i+1].x + w0.z*v[i+2].x + w0.w*v[i+3].x;
        float a1 = bias.y + w1.x*v[i].y + w1.y*v[i+1].y + w1.z*v[i+2].y + w1.w*v[i+3].y;
        float a2 = bias.z + w2.x*v[i].z + w2.y*v[i+1].z + w2.z*v[i+2].z + w2.w*v[i+3].z;
        float a3 = bias.w + w3.x*v[i].w + w3.y*v[i+1].w + w3.z*v[i+2].w + w3.w*v[i+3].w;
        float4 out;
        out.x = a0 / (1.f + __expf(-a0));
        out.y = a1 / (1.f + __expf(-a1));
        out.z = a2 / (1.f + __expf(-a2));
        out.w = a3 / (1.f + __expf(-a3));
        *(float4*)&g_xbc[((size_t)sb*L_ + l0 + i)*CONVD + ch] = out;
    }
}

// ============================================================================
// 4. dt softplus
// ============================================================================
__global__ void dt_kernel(const float* __restrict__ dt_bias) {
    size_t idx = (size_t)blockIdx.x * 256 + threadIdx.x;
    if (idx >= (size_t)2*B_*L_*NH) return;
    int h = (int)(idx % NH);
    size_t row = idx / NH;
    float v = g_zx[row*DPROJ + (DINNER + CONVD) + h] + dt_bias[h];
    g_dt[idx] = (v > 20.f) ? v : log1pf(__expf(v));
}

// ============================================================================
// 5. per-chunk cumsum (warp-parallel)
// ============================================================================
__global__ void cum_kernel_v2(const float* __restrict__ A_log) {
    int gw = blockIdx.x * 8 + (threadIdx.x >> 5);
    int lane = threadIdx.x & 31;
    if (gw >= 2*B_*NC*NH) return;
    int h = gw % NH;
    int c = (gw / NH) % NC;
    int sb = gw / (NH * NC);
    float An = -__expf(A_log[h]);
    size_t base = ((size_t)sb*L_ + c*CHUNKSZ + lane*4)*NH + h;
    float v0 = g_dt[base], v1 = g_dt[base + NH], v2 = g_dt[base + 2*NH], v3 = g_dt[base + 3*NH];
    float p0 = v0, p1 = p0 + v1, p2 = p1 + v2, p3 = p2 + v3;
    float incl = p3;
    #pragma unroll
    for (int o = 1; o < 32; o <<= 1) {
        float t = __shfl_up_sync(0xFFFFFFFFu, incl, o);
        if (lane >= o) incl += t;
    }
    float ex = incl - p3;
    g_cum[base]        = An * (ex + p0);
    g_cum[base + NH]   = An * (ex + p1);
    g_cum[base + 2*NH] = An * (ex + p2);
    g_cum[base + 3*NH] = An * (ex + p3);
}

// ============================================================================
// 6. Intra-chunk SSD via tensor cores (bf16 3-pass, unchanged)
// ============================================================================
#define CK_XT_H(p) (2048u + (uint32_t)(p)*16384u)
#define CK_XT_L(p) (34816u + (uint32_t)(p)*16384u)
#define CK_BW_H(p) (67584u + (uint32_t)(p)*8192u)
#define CK_BW_L(p) (83968u + (uint32_t)(p)*8192u)
#define CK_R1      100352u
#define CK_GH(p)   (CK_R1 + (uint32_t)(p)*16384u)
#define CK_GL(p)   (CK_R1 + 32768u + (uint32_t)(p)*16384u)
#define CK_SMEM    165888

__global__ void __launch_bounds__(256)
chunk_kernel_v2(const float* __restrict__ Dv) {
    extern __shared__ char smraw[];
    uint32_t sbase = smem_to_u32(smraw);
    float* cum_s = (float*)smraw;
    float* dts_s = (float*)(smraw + 512);
    float* wj_s  = (float*)(smraw + 1024);

    int bi = blockIdx.x, tid = threadIdx.x;
    int wid = tid >> 5, lane = tid & 31;
    int wm = wid & 3, wn = wid >> 2;
    int l2 = lane & 15;
    int h  = bi % NH;
    int c  = (bi / NH) % NC;
    int b  = (bi / (NH*NC)) % B_;
    int s  = bi / (NH*NC*B_);
    int sb  = s*B_ + b;
    int sbo = (1 - s)*B_ + b;
    size_t l0 = (size_t)c * CHUNKSZ;

    if (tid < 128) {
        size_t off = ((size_t)sb*L_ + l0 + tid)*NH + h;
        cum_s[tid] = g_cum[off];
        dts_s[tid] = g_dt[off];
    }
    __syncthreads();
    if (tid < 128) wj_s[tid] = dts_s[tid] * __expf(cum_s[127] - cum_s[tid]);
    __syncthreads();

    for (int idx = tid; idx < 128*64; idx += 256) {
        int j = idx >> 6, n = idx & 63;
        float cv = xbc_row(sb,  l0 + j)[576 + n];
        float bv = xbc_row(sbo, l0 + j)[512 + n];
        __nv_bfloat16 hh, ll;
        uint32_t so = swz((uint32_t)j*128 + n*2);
        split_bf16(cv, hh, ll);
        *(__nv_bfloat16*)(smraw + CK_R1 + so)         = hh;
        *(__nv_bfloat16*)(smraw + CK_R1 + 16384 + so) = ll;
        split_bf16(bv, hh, ll);
        *(__nv_bfloat16*)(smraw + CK_R1 + 32768 + so) = hh;
        *(__nv_bfloat16*)(smraw + CK_R1 + 49152 + so) = ll;
        float bw = bv * wj_s[j];
        split_bf16(bw, hh, ll);
        uint32_t st = swz((uint32_t)n*128 + (j & 63)*2);
        int pan = j >> 6;
        *(__nv_bfloat16*)(smraw + CK_BW_H(pan) + st) = hh;
        *(__nv_bfloat16*)(smraw + CK_BW_L(pan) + st) = ll;
    }
    for (int idx = tid; idx < 128*128; idx += 256) {
        int j = idx >> 7, p = idx & 127;
        float xv = xbc_row(sbo, l0 + j)[h*HD + p];
        __nv_bfloat16 hh, ll; split_bf16(xv, hh, ll);
        int pan = j >> 6;
        uint32_t st = swz((uint32_t)p*128 + (j & 63)*2);
        *(__nv_bfloat16*)(smraw + CK_XT_H(pan) + st) = hh;
        *(__nv_bfloat16*)(smraw + CK_XT_L(pan) + st) = ll;
    }
    __syncthreads();

    // phase A: G = C * B^T
    float accg[2][8][4];
    #pragma unroll
    for (int mt = 0; mt < 2; mt++)
        #pragma unroll
        for (int nt = 0; nt < 8; nt++)
            #pragma unroll
            for (int q = 0; q < 4; q++) accg[mt][nt][q] = 0.f;
    #pragma unroll
    for (int ks = 0; ks < 4; ks++) {
        uint32_t ah[2][4], al[2][4];
        #pragma unroll
        for (int mt = 0; mt < 2; mt++) {
            int row = wm*32 + mt*16 + (lane & 15);
            uint32_t off = swz((uint32_t)row*128 + ks*32 + ((lane >> 4) << 4));
            ldsm_x4(ah[mt], sbase + CK_R1 + off);
            ldsm_x4(al[mt], sbase + CK_R1 + 16384 + off);
        }
        #pragma unroll
        for (int nt = 0; nt < 8; nt++) {
            int row = wn*64 + nt*8 + (l2 & 7);
            uint32_t off = swz((uint32_t)row*128 + ks*32 + ((l2 >> 3) << 4));
            uint32_t bh[2], bl[2];
            ldsm_x2(bh, sbase + CK_R1 + 32768 + off);
            ldsm_x2(bl, sbase + CK_R1 + 49152 + off);
            #pragma unroll
            for (int mt = 0; mt < 2; mt++) {
                mma_bf16(accg[mt][nt], ah[mt], bh);
                mma_bf16(accg[mt][nt], ah[mt], bl);
                mma_bf16(accg[mt][nt], al[mt], bh);
            }
        }
    }
    __syncthreads();

    {
        int r0 = lane >> 2, cj = 2*(lane & 3);
        #pragma unroll
        for (int mt = 0; mt < 2; mt++) {
            #pragma unroll
            for (int nt = 0; nt < 8; nt++) {
                int j0 = wn*64 + nt*8 + cj;
                int jl = (j0 & 63);
                #pragma unroll
                for (int half = 0; half < 2; half++) {
                    int i = wm*32 + mt*16 + r0 + half*8;
                    float ci = cum_s[i];
                    float g0 = (j0   <= i) ? accg[mt][nt][half*2]   * __expf(ci - cum_s[j0])   * dts_s[j0]   : 0.f;
                    float g1 = (j0+1 <= i) ? accg[mt][nt][half*2+1] * __expf(ci - cum_s[j0+1]) * dts_s[j0+1] : 0.f;
                    __nv_bfloat16 h0, l0b, h1, l1b;
                    split_bf16(g0, h0, l0b); split_bf16(g1, h1, l1b);
                    uint32_t st = swz((uint32_t)i*128 + jl*2);
                    *(__nv_bfloat162*)(smraw + CK_GH(wn) + st) = __nv_bfloat162(h0, h1);
                    *(__nv_bfloat162*)(smraw + CK_GL(wn) + st) = __nv_bfloat162(l0b, l1b);
                }
            }
        }
    }
    __syncthreads();

    // phase B: Y = G @ X
    {
        float accy[2][8][4];
        #pragma unroll
        for (int mt = 0; mt < 2; mt++)
            #pragma unroll
            for (int nt = 0; nt < 8; nt++)
                #pragma unroll
                for (int q = 0; q < 4; q++) accy[mt][nt][q] = 0.f;
        #pragma unroll
        for (int pan = 0; pan < 2; pan++) {
            #pragma unroll
            for (int ks = 0; ks < 4; ks++) {
                uint32_t gh[2][4], gl[2][4];
                #pragma unroll
                for (int mt = 0; mt < 2; mt++) {
                    int row = wm*32 + mt*16 + (lane & 15);
                    uint32_t off = swz((uint32_t)row*128 + ks*32 + ((lane >> 4) << 4));
                    ldsm_x4(gh[mt], sbase + CK_GH(pan) + off);
                    ldsm_x4(gl[mt], sbase + CK_GL(pan) + off);
                }
                #pragma unroll
                for (int nt = 0; nt < 8; nt++) {
                    int row = wn*64 + nt*8 + (l2 & 7);
                    uint32_t off = swz((uint32_t)row*128 + ks*32 + ((l2 >> 3) << 4));
                    uint32_t xh[2], xl[2];
                    ldsm_x2(xh, sbase + CK_XT_H(pan) + off);
                    ldsm_x2(xl, sbase + CK_XT_L(pan) + off);
                    #pragma unroll
                    for (int mt = 0; mt < 2; mt++) {
                        mma_bf16(accy[mt][nt], gh[mt], xh);
                        mma_bf16(accy[mt][nt], gh[mt], xl);
                        mma_bf16(accy[mt][nt], gl[mt], xh);
                    }
                }
            }
        }
        float Dh = Dv[h];
        int r0 = lane >> 2, cp = 2*(lane & 3);
        #pragma unroll
        for (int mt = 0; mt < 2; mt++) {
            #pragma unroll
            for (int nt = 0; nt < 8; nt++) {
                int p0 = wn*64 + nt*8 + cp;
                #pragma unroll
                for (int half = 0; half < 2; half++) {
                    int i = wm*32 + mt*16 + r0 + half*8;
                    int ipan = i >> 6;
                    uint32_t b0 = swz((uint32_t)p0*128 + (i & 63)*2);
                    uint32_t b1 = swz((uint32_t)(p0+1)*128 + (i & 63)*2);
                    float x0 = __bfloat162float(*(__nv_bfloat16*)(smraw + CK_XT_H(ipan) + b0))
                             + __bfloat162float(*(__nv_bfloat16*)(smraw + CK_XT_L(ipan) + b0));
                    float x1 = __bfloat162float(*(__nv_bfloat16*)(smraw + CK_XT_H(ipan) + b1))
                             + __bfloat162float(*(__nv_bfloat16*)(smraw + CK_XT_L(ipan) + b1));
                    size_t off = ((size_t)sb*L_ + l0 + i)*DINNER + h*HD + p0;
                    *(float2*)&g_y[off] = make_float2(accy[mt][nt][half*2] + Dh*x0,
                                                      accy[mt][nt][half*2+1] + Dh*x1);
                }
            }
        }
    }

    // phase C: S = X^T @ Bw
    {
        float accs[2][4][4];
        #pragma unroll
        for (int mt = 0; mt < 2; mt++)
            #pragma unroll
            for (int nt = 0; nt < 4; nt++)
                #pragma unroll
                for (int q = 0; q < 4; q++) accs[mt][nt][q] = 0.f;
        #pragma unroll
        for (int pan = 0; pan < 2; pan++) {
            #pragma unroll
            for (int ks = 0; ks < 4; ks++) {
                uint32_t xh[2][4], xl[2][4];
                #pragma unroll
                for (int mt = 0; mt < 2; mt++) {
                    int row = wm*32 + mt*16 + (lane & 15);
                    uint32_t off = swz((uint32_t)row*128 + ks*32 + ((lane >> 4) << 4));
                    ldsm_x4(xh[mt], sbase + CK_XT_H(pan) + off);
                    ldsm_x4(xl[mt], sbase + CK_XT_L(pan) + off);
                }
                #pragma unroll
                for (int nt = 0; nt < 4; nt++) {
                    int row = wn*32 + nt*8 + (l2 & 7);
                    uint32_t off = swz((uint32_t)row*128 + ks*32 + ((l2 >> 3) << 4));
                    uint32_t bwh[2], bwl[2];
                    ldsm_x2(bwh, sbase + CK_BW_H(pan) + off);
                    ldsm_x2(bwl, sbase + CK_BW_L(pan) + off);
                    #pragma unroll
                    for (int mt = 0; mt < 2; mt++) {
                        mma_bf16(accs[mt][nt], xh[mt], bwh);
                        mma_bf16(accs[mt][nt], xh[mt], bwl);
                        mma_bf16(accs[mt][nt], xl[mt], bwh);
                    }
                }
            }
        }
        size_t sb0 = (size_t)bi * (HD*DSTATE);
        int r0 = lane >> 2, cn = 2*(lane & 3);
        #pragma unroll
        for (int mt = 0; mt < 2; mt++) {
            #pragma unroll
            for (int nt = 0; nt < 4; nt++) {
                int n0 = wn*32 + nt*8 + cn;
                #pragma unroll
                for (int half = 0; half < 2; half++) {
                    int p = wm*32 + mt*16 + r0 + half*8;
                    *(float2*)&g_state[sb0 + (size_t)p*64 + n0] =
                        make_float2(accs[mt][nt][half*2], accs[mt][nt][half*2+1]);
                }
            }
        }
    }
}

// ============================================================================
// 7. Inter-chunk scan
// ============================================================================
__global__ void scan_kernel_v2() {
    int t   = blockIdx.x >> 3;
    int seg = blockIdx.x & 7;
    int h = t % NH;
    int sb = t / NH;
    int off0 = seg * 1024 + threadIdx.x * 4;
    float4 hreg = make_float4(0.f, 0.f, 0.f, 0.f);
    for (int c = 0; c < NC; c++) {
        float dec = __expf(g_cum[((size_t)sb*L_ + c*CHUNKSZ + 127)*NH + h]);
        size_t o = (((size_t)sb*NC + c)*NH + h) * (HD*DSTATE) + off0;
        *(float4*)&g_hprev[o] = hreg;
        float4 st = *(const float4*)&g_state[o];
        hreg.x = hreg.x*dec + st.x;
        hreg.y = hreg.y*dec + st.y;
        hreg.z = hreg.z*dec + st.z;
        hreg.w = hreg.w*dec + st.w;
    }
}

// ============================================================================
// 8. Inter-chunk contribution via tensor cores (bf16 3-pass, unchanged)
// ============================================================================
__global__ void __launch_bounds__(256)
interchunk_kernel_v2() {
    extern __shared__ char smraw[];
    uint32_t sbase = smem_to_u32(smraw);
    float* cum_s = (float*)smraw;

    int bi = blockIdx.x, tid = threadIdx.x;
    int wid = tid >> 5, lane = tid & 31;
    int wm = wid & 3, wn = wid >> 2;
    int l2 = lane & 15;
    int h  = bi % NH;
    int c  = (bi / NH) % NC;
    int b  = (bi / (NH*NC)) % B_;
    int s  = bi / (NH*NC*B_);
    int sb = s*B_ + b;
    size_t l0 = (size_t)c * CHUNKSZ;
    size_t hbase = (size_t)bi * (HD*DSTATE);

    if (tid < 128) cum_s[tid] = g_cum[((size_t)sb*L_ + l0 + tid)*NH + h];

    for (int idx = tid; idx < 128*64; idx += 256) {
        int r = idx >> 6, n = idx & 63;
        float cv = xbc_row(sb, l0 + r)[576 + n];
        float hv = g_hprev[hbase + idx];
        __nv_bfloat16 hh, ll;
        uint32_t so = swz((uint32_t)r*128 + n*2);
        split_bf16(cv, hh, ll);
        *(__nv_bfloat16*)(smraw + 1024 + so)         = hh;
        *(__nv_bfloat16*)(smraw + 1024 + 16384 + so) = ll;
        split_bf16(hv, hh, ll);
        *(__nv_bfloat16*)(smraw + 1024 + 32768 + so) = hh;
        *(__nv_bfloat16*)(smraw + 1024 + 49152 + so) = ll;
    }
    __syncthreads();

    float acc[2][8][4];
    #pragma unroll
    for (int mt = 0; mt < 2; mt++)
        #pragma unroll
        for (int nt = 0; nt < 8; nt++)
            #pragma unroll
            for (int q = 0; q < 4; q++) acc[mt][nt][q] = 0.f;
    #pragma unroll
    for (int ks = 0; ks < 4; ks++) {
        uint32_t ah[2][4], al[2][4];
        #pragma unroll
        for (int mt = 0; mt < 2; mt++) {
            int row = wm*32 + mt*16 + (lane & 15);
            uint32_t off = swz((uint32_t)row*128 + ks*32 + ((lane >> 4) << 4));
            ldsm_x4(ah[mt], sbase + 1024 + off);
            ldsm_x4(al[mt], sbase + 1024 + 16384 + off);
        }
        #pragma unroll
        for (int nt = 0; nt < 8; nt++) {
            int row = wn*64 + nt*8 + (l2 & 7);
            uint32_t off = swz((uint32_t)row*128 + ks*32 + ((l2 >> 3) << 4));
            uint32_t hh[2], hl[2];
            ldsm_x2(hh, sbase + 1024 + 32768 + off);
            ldsm_x2(hl, sbase + 1024 + 49152 + off);
            #pragma unroll
            for (int mt = 0; mt < 2; mt++) {
                mma_bf16(acc[mt][nt], ah[mt], hh);
                mma_bf16(acc[mt][nt], ah[mt], hl);
                mma_bf16(acc[mt][nt], al[mt], hh);
            }
        }
    }

    int r0 = lane >> 2, cp = 2*(lane & 3);
    #pragma unroll
    for (int mt = 0; mt < 2; mt++) {
        #pragma unroll
        for (int nt = 0; nt < 8; nt++) {
            int p = wn*64 + nt*8 + cp;
            #pragma unroll
            for (int half = 0; half < 2; half++) {
                int i = wm*32 + mt*16 + r0 + half*8;
                float sc = __expf(cum_s[i]);
                size_t off = ((size_t)sb*L_ + l0 + i)*DINNER + h*HD + p;
                float2 v = *(float2*)&g_y[off];
                v.x += sc * acc[mt][nt][half*2];
                v.y += sc * acc[mt][nt][half*2+1];
                *(float2*)&g_y[off] = v;
            }
        }
    }
}

// ============================================================================
// 9. Gated RMSNorm -> fp16 A for out_proj
// ============================================================================
__global__ void rmsnorm_kernel(const float* __restrict__ norm_w) {
    int row = blockIdx.x;
    int tid = threadIdx.x;
    __shared__ float red[4];
    size_t ybase = (size_t)row * DINNER;
    size_t zbase = (size_t)row * DPROJ;
    float g[4];
    float ss = 0.f;
    #pragma unroll
    for (int t = 0; t < 4; t++) {
        int d = tid + 128*t;
        float z = g_zx[zbase + d];
        float yv = g_y[ybase + d];
        float gg = yv * (z / (1.f + __expf(-z)));
        g[t] = gg;
        ss += gg*gg;
    }
    #pragma unroll
    for (int o = 16; o > 0; o >>= 1) ss += __shfl_xor_sync(0xFFFFFFFFu, ss, o);
    if ((tid & 31) == 0) red[tid >> 5] = ss;
    __syncthreads();
    float tot = red[0] + red[1] + red[2] + red[3];
    float scale = rsqrtf(tot / (float)DINNER + 1e-5f);
    #pragma unroll
    for (int t = 0; t < 4; t++) {
        int d = tid + 128*t;
        float v = g[t] * scale * norm_w[d];
        g_a16[ybase + d] = __float2half_rn(v);
    }
}

// ============================================================================
extern "C" void kernel_launch(void* const* d_in, const int* in_sizes, int n_in,
                              void* d_out, int out_size) {
    const float* left   = (const float*)d_in[0];
    const float* right  = (const float*)d_in[1];
    const float* dw     = (const float*)d_in[2];
    const float* db     = (const float*)d_in[3];
    const float* inpw   = (const float*)d_in[4];
    const float* cw     = (const float*)d_in[5];
    const float* cb     = (const float*)d_in[6];
    const float* dtb    = (const float*)d_in[7];
    const float* alog   = (const float*)d_in[8];
    const float* Dv     = (const float*)d_in[9];
    const float* nw     = (const float*)d_in[10];
    const float* outw   = (const float*)d_in[11];
    float* out          = (float*)d_out;

    float *p_zx;
    __half *p_a16, *p_bh, *p_bl;
    cudaGetSymbolAddress((void**)&p_zx,  g_zx);
    cudaGetSymbolAddress((void**)&p_a16, g_a16);
    cudaGetSymbolAddress((void**)&p_bh,  g_bh);
    cudaGetSymbolAddress((void**)&p_bl,  g_bl);

    const int ds_smem  = (DMODEL*48 + 16*48) * 4;
    const int mma_smem = 3 * GF_STAGE;   // 147456
    const int ic_smem  = 66560;
    cudaFuncSetAttribute(downsample_kernel,    cudaFuncAttributeMaxDynamicSharedMemorySize, ds_smem);
    cudaFuncSetAttribute(mma_gemm,             cudaFuncAttributeMaxDynamicSharedMemorySize, mma_smem);
    cudaFuncSetAttribute(chunk_kernel_v2,      cudaFuncAttributeMaxDynamicSharedMemorySize, CK_SMEM);
    cudaFuncSetAttribute(interchunk_kernel_v2, cudaFuncAttributeMaxDynamicSharedMemorySize, ic_smem);

    const int M = 2*B_*L_;   // 65536

    // 1. downsample (emits fp16 A)
    downsample_kernel<<<2*B_*HO*(WO/16), 256, ds_smem>>>(left, right, dw, db);

    // 2. in_proj (A fp16, B split-fp16, 2-MMA)
    {
        size_t nb = (size_t)DPROJ_PAD * DMODEL;
        cvt_split_pad<<<(unsigned)((nb + 255)/256), 256>>>(inpw, p_bh, p_bl, DPROJ, DMODEL, DPROJ_PAD);
        dim3 grid(DPROJ_PAD/128, M/128);
        mma_gemm<<<grid, 256, mma_smem>>>(p_a16, p_bh, p_bl, p_zx, M, DPROJ, DMODEL);
    }

    // 3. conv+silu (stream 0 only; stream 1 read raw from g_zx downstream)
    {
        int total = B_ * (L_/8) * (CONVD/4);
        conv_split_kernel_v2<<<(total + 255)/256, 256>>>(cw, cb);
    }
    {
        size_t tot = (size_t)M*NH;
        dt_kernel<<<(unsigned)((tot + 255)/256), 256>>>(dtb);
    }
    cum_kernel_v2<<<2*B_*NC*NH/8, 256>>>(alog);

    // 6-8. SSD (bf16 3-pass, unchanged)
    chunk_kernel_v2<<<2*B_*NC*NH, 256, CK_SMEM>>>(Dv);
    scan_kernel_v2<<<2*B_*NH*8, 256>>>();
    interchunk_kernel_v2<<<2*B_*NC*NH, 256, ic_smem>>>();

    // 9. rmsnorm (emits fp16 A)
    rmsnorm_kernel<<<M, 128>>>(nw);

    // 10. out_proj
    {
        size_t nb = (size_t)DMODEL * DINNER;
        cvt_split_pad<<<(unsigned)((nb + 255)/256), 256>>>(outw, p_bh, p_bl, DMODEL, DINNER, DMODEL);
        dim3 grid(DMODEL/128, M/128);
        mma_gemm<<<grid, 256, mma_smem>>>(p_a16, p_bh, p_bl, out, M, DMODEL, DINNER);
    }
}